// round 1
// baseline (speedup 1.0000x reference)
#include <cuda_runtime.h>
#include <math.h>

#define BB 4
#define TT 2048
#define CC 1024
#define HH 128
#define SCALE 0.08838834764831845f  // 1/sqrt(128)

// Scratch: static device globals (no allocation allowed in kernel_launch)
__device__ float g_q[BB * TT * HH];
__device__ float g_k[BB * TT * HH];
__device__ float g_v[BB * TT * HH];
__device__ float g_st[(size_t)BB * TT * TT];  // ST[b][s][t] = scale * k[s].q[t], -inf if t<s
__device__ float g_m[BB * TT];                // column max (per key s)
__device__ float g_rd[BB * TT];               // 1/column sum

// ---------------------------------------------------------------------------
// K1: QKV projection. grid.x = (B*T)/128 row tiles, grid.y in {0,1,2} picks W.
// 128x128 tile, K-chunk 32, 256 threads, 8x8 microtile.
// ---------------------------------------------------------------------------
__global__ __launch_bounds__(256) void qkv_kernel(
    const float* __restrict__ x,
    const float* __restrict__ Wq,
    const float* __restrict__ Wk,
    const float* __restrict__ Wv)
{
    __shared__ float As[32][129];   // [k][row], padded
    __shared__ float Bs[32][128];   // [k][h]

    const float* W = (blockIdx.y == 0) ? Wq : (blockIdx.y == 1) ? Wk : Wv;
    float* out     = (blockIdx.y == 0) ? g_q : (blockIdx.y == 1) ? g_k : g_v;

    const int row0 = blockIdx.x * 128;
    const int tid  = threadIdx.x;
    const int ty   = tid >> 4;   // 0..15
    const int tx   = tid & 15;   // 0..15

    float acc[8][8] = {};

    for (int k0 = 0; k0 < CC; k0 += 32) {
        #pragma unroll
        for (int i = 0; i < 16; i++) {
            int idx = tid + i * 256;
            int r = idx >> 5, c = idx & 31;
            As[c][r] = x[(size_t)(row0 + r) * CC + k0 + c];
        }
        #pragma unroll
        for (int i = 0; i < 16; i++) {
            int idx = tid + i * 256;
            int kk = idx >> 7, h = idx & 127;
            Bs[kk][h] = W[(size_t)(k0 + kk) * HH + h];
        }
        __syncthreads();

        #pragma unroll
        for (int kk = 0; kk < 32; kk++) {
            float a[8], bb[8];
            #pragma unroll
            for (int i = 0; i < 8; i++) a[i] = As[kk][ty * 8 + i];
            #pragma unroll
            for (int j = 0; j < 8; j++) bb[j] = Bs[kk][tx * 8 + j];
            #pragma unroll
            for (int i = 0; i < 8; i++)
                #pragma unroll
                for (int j = 0; j < 8; j++)
                    acc[i][j] += a[i] * bb[j];
        }
        __syncthreads();
    }

    #pragma unroll
    for (int i = 0; i < 8; i++)
        #pragma unroll
        for (int j = 0; j < 8; j++)
            out[(size_t)(row0 + ty * 8 + i) * HH + tx * 8 + j] = acc[i][j];
}

// ---------------------------------------------------------------------------
// K2: ST[b][s][t] = scale * dot(k[s], q[t]) for t >= s, else -inf.
// grid = (T/128 t-tiles, T/128 s-tiles, B). 128x128 tile, K=H=128 in chunks of 32.
// ---------------------------------------------------------------------------
__global__ __launch_bounds__(256) void st_kernel()
{
    const int b  = blockIdx.z;
    const int t0 = blockIdx.x * 128;
    const int s0 = blockIdx.y * 128;
    float* stb = g_st + (size_t)b * TT * TT;

    const int tid = threadIdx.x;
    const int ty  = tid >> 4;
    const int tx  = tid & 15;

    if (t0 + 127 < s0) {
        // fully masked tile: write -inf (buffer must be deterministic every call)
        #pragma unroll
        for (int i = 0; i < 8; i++)
            #pragma unroll
            for (int j = 0; j < 8; j++)
                stb[(size_t)(s0 + ty * 8 + i) * TT + t0 + tx * 8 + j] = -INFINITY;
        return;
    }

    __shared__ float Ks[32][129];  // [k][s-row]
    __shared__ float Qs[32][129];  // [k][t-row]
    const float* kp = g_k + (size_t)b * TT * HH;
    const float* qp = g_q + (size_t)b * TT * HH;

    float acc[8][8] = {};

    for (int k0 = 0; k0 < HH; k0 += 32) {
        #pragma unroll
        for (int i = 0; i < 16; i++) {
            int idx = tid + i * 256;
            int r = idx >> 5, c = idx & 31;
            Ks[c][r] = kp[(size_t)(s0 + r) * HH + k0 + c];
            Qs[c][r] = qp[(size_t)(t0 + r) * HH + k0 + c];
        }
        __syncthreads();

        #pragma unroll
        for (int kk = 0; kk < 32; kk++) {
            float a[8], bb[8];
            #pragma unroll
            for (int i = 0; i < 8; i++) a[i] = Ks[kk][ty * 8 + i];
            #pragma unroll
            for (int j = 0; j < 8; j++) bb[j] = Qs[kk][tx * 8 + j];
            #pragma unroll
            for (int i = 0; i < 8; i++)
                #pragma unroll
                for (int j = 0; j < 8; j++)
                    acc[i][j] += a[i] * bb[j];
        }
        __syncthreads();
    }

    #pragma unroll
    for (int i = 0; i < 8; i++) {
        int s = s0 + ty * 8 + i;
        #pragma unroll
        for (int j = 0; j < 8; j++) {
            int t = t0 + tx * 8 + j;
            stb[(size_t)s * TT + t] = (t >= s) ? acc[i][j] * SCALE : -INFINITY;
        }
    }
}

// ---------------------------------------------------------------------------
// K3: per-(b,s) column stats over t: max and 1/sum(exp). Row of ST is
// contiguous in t; masked entries are -inf so exp contributes 0.
// grid = (T, B), 256 threads.
// ---------------------------------------------------------------------------
__global__ __launch_bounds__(256) void stats_kernel()
{
    const int s = blockIdx.x;
    const int b = blockIdx.y;
    const float* row = g_st + (size_t)b * TT * TT + (size_t)s * TT;
    const int tid = threadIdx.x;

    __shared__ float red[256];

    float m = -INFINITY;
    for (int t = tid; t < TT; t += 256) m = fmaxf(m, row[t]);
    red[tid] = m;
    __syncthreads();
    for (int off = 128; off > 0; off >>= 1) {
        if (tid < off) red[tid] = fmaxf(red[tid], red[tid + off]);
        __syncthreads();
    }
    const float mv = red[0];
    __syncthreads();

    float d = 0.0f;
    for (int t = tid; t < TT; t += 256) d += __expf(row[t] - mv);
    red[tid] = d;
    __syncthreads();
    for (int off = 128; off > 0; off >>= 1) {
        if (tid < off) red[tid] += red[tid + off];
        __syncthreads();
    }
    if (tid == 0) {
        g_m[b * TT + s]  = mv;
        g_rd[b * TT + s] = 1.0f / red[0];
    }
}

// ---------------------------------------------------------------------------
// K4: out[b][t][h] = sum_s P[s][t] * v[s][h], P[s][t] = exp(ST[s][t]-m[s])*rd[s].
// Tile 64(t) x 128(h), 256 threads, 4x8 microtile, s-chunks of 32.
// Only s < t0+64 can contribute (masked entries exp to 0 inside the chunk).
// grid = (T/64, B).
// ---------------------------------------------------------------------------
__global__ __launch_bounds__(256) void out_kernel(float* __restrict__ out)
{
    const int b  = blockIdx.y;
    const int t0 = blockIdx.x * 64;

    const float* stb = g_st + (size_t)b * TT * TT;
    const float* vp  = g_v + (size_t)b * TT * HH;
    const float* mp  = g_m + b * TT;
    const float* rdp = g_rd + b * TT;

    const int tid = threadIdx.x;
    const int ty  = tid >> 4;   // 0..15 -> t rows (x4)
    const int tx  = tid & 15;   // 0..15 -> h cols (x8)

    __shared__ float Ps[32][64];   // [s][t]
    __shared__ float Vs[32][128];  // [s][h]

    float acc[4][8] = {};

    const int send = t0 + 64;  // s >= t0+64 fully masked for this t-tile
    for (int sc = 0; sc < send; sc += 32) {
        #pragma unroll
        for (int i = 0; i < 8; i++) {
            int idx = tid + i * 256;
            int ss = idx >> 6, ttl = idx & 63;
            int s = sc + ss;
            float val = stb[(size_t)s * TT + t0 + ttl];
            Ps[ss][ttl] = __expf(val - mp[s]) * rdp[s];
        }
        #pragma unroll
        for (int i = 0; i < 16; i++) {
            int idx = tid + i * 256;
            int ss = idx >> 7, h = idx & 127;
            Vs[ss][h] = vp[(size_t)(sc + ss) * HH + h];
        }
        __syncthreads();

        #pragma unroll
        for (int kk = 0; kk < 32; kk++) {
            float a[4], bb[8];
            #pragma unroll
            for (int i = 0; i < 4; i++) a[i] = Ps[kk][ty * 4 + i];
            #pragma unroll
            for (int j = 0; j < 8; j++) bb[j] = Vs[kk][tx * 8 + j];
            #pragma unroll
            for (int i = 0; i < 4; i++)
                #pragma unroll
                for (int j = 0; j < 8; j++)
                    acc[i][j] += a[i] * bb[j];
        }
        __syncthreads();
    }

    #pragma unroll
    for (int i = 0; i < 4; i++)
        #pragma unroll
        for (int j = 0; j < 8; j++)
            out[((size_t)b * TT + t0 + ty * 4 + i) * HH + tx * 8 + j] = acc[i][j];
}

extern "C" void kernel_launch(void* const* d_in, const int* in_sizes, int n_in,
                              void* d_out, int out_size)
{
    const float* x  = (const float*)d_in[0];
    const float* Wq = (const float*)d_in[1];
    const float* Wk = (const float*)d_in[2];
    const float* Wv = (const float*)d_in[3];
    float* out = (float*)d_out;

    qkv_kernel<<<dim3((BB * TT) / 128, 3), 256>>>(x, Wq, Wk, Wv);
    st_kernel<<<dim3(TT / 128, TT / 128, BB), 256>>>();
    stats_kernel<<<dim3(TT, BB), 256>>>();
    out_kernel<<<dim3(TT / 64, BB), 256>>>(out);
}

// round 2
// speedup vs baseline: 1.3132x; 1.3132x over previous
#include <cuda_runtime.h>
#include <math.h>

#define BB 4
#define TT 2048
#define CC 1024
#define HH 128
#define SCALE 0.08838834764831845f  // 1/sqrt(128)

#define NS   8     // split-K segments for out_kernel
#define SLEN 256   // keys per segment (NS*SLEN == TT)

// Scratch: static device globals (no allocation allowed in kernel_launch)
__device__ float g_q[BB * TT * HH];
__device__ float g_k[BB * TT * HH];
__device__ float g_v[BB * TT * HH];
__device__ float g_st[(size_t)BB * TT * TT];     // ST[b][s][t]; only tiles with t0+127>=s0 written
__device__ float g_m[BB * TT];                   // column max (per key s)
__device__ float g_rd[BB * TT];                  // 1/column sum
__device__ float g_part[(size_t)NS * BB * TT * HH];  // split-K partials (32 MB)

// ---------------------------------------------------------------------------
// K1: QKV projection. 64x128 tiles, 256 threads, 4x8 microtile, K-chunk 32.
// grid = ((B*T)/64, 3)
// ---------------------------------------------------------------------------
__global__ __launch_bounds__(256) void qkv_kernel(
    const float* __restrict__ x,
    const float* __restrict__ Wq,
    const float* __restrict__ Wk,
    const float* __restrict__ Wv)
{
    __shared__ float As[32][65];    // [k][row], padded
    __shared__ float Bs[32][128];   // [k][h]

    const float* W = (blockIdx.y == 0) ? Wq : (blockIdx.y == 1) ? Wk : Wv;
    float* out     = (blockIdx.y == 0) ? g_q : (blockIdx.y == 1) ? g_k : g_v;

    const int row0 = blockIdx.x * 64;
    const int tid  = threadIdx.x;
    const int ty   = tid >> 4;   // 0..15 -> 4 rows each
    const int tx   = tid & 15;   // 0..15 -> 8 cols each

    float acc[4][8] = {};

    for (int k0 = 0; k0 < CC; k0 += 32) {
        #pragma unroll
        for (int i = 0; i < 8; i++) {
            int idx = tid + i * 256;
            int r = idx >> 5, c = idx & 31;
            As[c][r] = x[(size_t)(row0 + r) * CC + k0 + c];
        }
        #pragma unroll
        for (int i = 0; i < 16; i++) {
            int idx = tid + i * 256;
            int kk = idx >> 7, h = idx & 127;
            Bs[kk][h] = W[(size_t)(k0 + kk) * HH + h];
        }
        __syncthreads();

        #pragma unroll
        for (int kk = 0; kk < 32; kk++) {
            float a[4], bb[8];
            #pragma unroll
            for (int i = 0; i < 4; i++) a[i] = As[kk][ty * 4 + i];
            #pragma unroll
            for (int j = 0; j < 8; j++) bb[j] = Bs[kk][tx * 8 + j];
            #pragma unroll
            for (int i = 0; i < 4; i++)
                #pragma unroll
                for (int j = 0; j < 8; j++)
                    acc[i][j] += a[i] * bb[j];
        }
        __syncthreads();
    }

    #pragma unroll
    for (int i = 0; i < 4; i++)
        #pragma unroll
        for (int j = 0; j < 8; j++)
            out[(size_t)(row0 + ty * 4 + i) * HH + tx * 8 + j] = acc[i][j];
}

// ---------------------------------------------------------------------------
// K2: ST[b][s][t] = scale * dot(k[s], q[t]) for t >= s, else -inf (within
// tiles touching the diagonal or below). Fully-masked tiles are SKIPPED
// (never written, never read downstream).
// grid = (T/128 t-tiles, T/128 s-tiles, B).
// ---------------------------------------------------------------------------
__global__ __launch_bounds__(256) void st_kernel()
{
    const int b  = blockIdx.z;
    const int t0 = blockIdx.x * 128;
    const int s0 = blockIdx.y * 128;

    if (t0 + 127 < s0) return;  // fully masked: skip entirely

    float* stb = g_st + (size_t)b * TT * TT;
    const int tid = threadIdx.x;
    const int ty  = tid >> 4;
    const int tx  = tid & 15;

    __shared__ float Ks[32][129];  // [k][s-row]
    __shared__ float Qs[32][129];  // [k][t-row]
    const float* kp = g_k + (size_t)b * TT * HH;
    const float* qp = g_q + (size_t)b * TT * HH;

    float acc[8][8] = {};

    for (int k0 = 0; k0 < HH; k0 += 32) {
        #pragma unroll
        for (int i = 0; i < 16; i++) {
            int idx = tid + i * 256;
            int r = idx >> 5, c = idx & 31;
            Ks[c][r] = kp[(size_t)(s0 + r) * HH + k0 + c];
            Qs[c][r] = qp[(size_t)(t0 + r) * HH + k0 + c];
        }
        __syncthreads();

        #pragma unroll
        for (int kk = 0; kk < 32; kk++) {
            float a[8], bb[8];
            #pragma unroll
            for (int i = 0; i < 8; i++) a[i] = Ks[kk][ty * 8 + i];
            #pragma unroll
            for (int j = 0; j < 8; j++) bb[j] = Qs[kk][tx * 8 + j];
            #pragma unroll
            for (int i = 0; i < 8; i++)
                #pragma unroll
                for (int j = 0; j < 8; j++)
                    acc[i][j] += a[i] * bb[j];
        }
        __syncthreads();
    }

    #pragma unroll
    for (int i = 0; i < 8; i++) {
        int s = s0 + ty * 8 + i;
        #pragma unroll
        for (int j = 0; j < 8; j++) {
            int t = t0 + tx * 8 + j;
            stb[(size_t)s * TT + t] = (t >= s) ? acc[i][j] * SCALE : -INFINITY;
        }
    }
}

// ---------------------------------------------------------------------------
// K3: per-(b,s) column stats over t in [s, T): max and 1/sum(exp).
// grid = (T, B), 256 threads.
// ---------------------------------------------------------------------------
__global__ __launch_bounds__(256) void stats_kernel()
{
    const int s = blockIdx.x;
    const int b = blockIdx.y;
    const float* row = g_st + (size_t)b * TT * TT + (size_t)s * TT;
    const int tid = threadIdx.x;

    __shared__ float red[256];

    float m = -INFINITY;
    for (int t = s + tid; t < TT; t += 256) m = fmaxf(m, row[t]);
    red[tid] = m;
    __syncthreads();
    for (int off = 128; off > 0; off >>= 1) {
        if (tid < off) red[tid] = fmaxf(red[tid], red[tid + off]);
        __syncthreads();
    }
    const float mv = red[0];
    __syncthreads();

    float d = 0.0f;
    for (int t = s + tid; t < TT; t += 256) d += __expf(row[t] - mv);
    red[tid] = d;
    __syncthreads();
    for (int off = 128; off > 0; off >>= 1) {
        if (tid < off) red[tid] += red[tid + off];
        __syncthreads();
    }
    if (tid == 0) {
        g_m[b * TT + s]  = mv;
        g_rd[b * TT + s] = 1.0f / red[0];
    }
}

// ---------------------------------------------------------------------------
// K4: split-K partial of out: part[js][b][t][h] += sum over s in segment js
// of P[s][t]*v[s][h]. 128(t) x 128(h) tile, 256 threads, 8x8 microtile.
// grid = (T/128, NS, B). Block active iff its segment intersects [0, t0+128).
// Deterministic: fixed segmentation, partials reduced in fixed order by K5.
// ---------------------------------------------------------------------------
__global__ __launch_bounds__(256) void out_kernel()
{
    const int b  = blockIdx.z;
    const int t0 = blockIdx.x * 128;
    const int js = blockIdx.y;

    const int s_begin = js * SLEN;
    const int s_end_v = (js + 1) * SLEN;
    const int s_end   = (s_end_v < t0 + 128) ? s_end_v : (t0 + 128);
    if (s_begin >= s_end) return;  // inactive segment for this t-tile

    const float* stb = g_st + (size_t)b * TT * TT;
    const float* vp  = g_v + (size_t)b * TT * HH;
    const float* mp  = g_m + b * TT;
    const float* rdp = g_rd + b * TT;
    float* part = g_part + ((size_t)js * BB + b) * TT * HH;

    const int tid = threadIdx.x;
    const int ty  = tid >> 4;   // t rows (x8)
    const int tx  = tid & 15;   // h cols (x8)

    __shared__ float Ps[32][128];   // [s][t]
    __shared__ float Vs[32][128];   // [s][h]

    float acc[8][8] = {};

    for (int sc = s_begin; sc < s_end; sc += 32) {
        #pragma unroll
        for (int i = 0; i < 16; i++) {
            int idx = tid + i * 256;
            int ss = idx >> 7, ttl = idx & 127;
            int s = sc + ss;
            float val = stb[(size_t)s * TT + t0 + ttl];  // -inf above diag -> exp = 0
            Ps[ss][ttl] = __expf(val - mp[s]) * rdp[s];
        }
        #pragma unroll
        for (int i = 0; i < 16; i++) {
            int idx = tid + i * 256;
            int ss = idx >> 7, h = idx & 127;
            Vs[ss][h] = vp[(size_t)(sc + ss) * HH + h];
        }
        __syncthreads();

        #pragma unroll
        for (int kk = 0; kk < 32; kk++) {
            float a[8], bb[8];
            #pragma unroll
            for (int i = 0; i < 8; i++) a[i] = Ps[kk][ty * 8 + i];
            #pragma unroll
            for (int j = 0; j < 8; j++) bb[j] = Vs[kk][tx * 8 + j];
            #pragma unroll
            for (int i = 0; i < 8; i++)
                #pragma unroll
                for (int j = 0; j < 8; j++)
                    acc[i][j] += a[i] * bb[j];
        }
        __syncthreads();
    }

    #pragma unroll
    for (int i = 0; i < 8; i++)
        #pragma unroll
        for (int j = 0; j < 8; j++)
            part[(size_t)(t0 + ty * 8 + i) * HH + tx * 8 + j] = acc[i][j];
}

// ---------------------------------------------------------------------------
// K5: reduce partials -> out. Each element knows how many segments were
// active for its t-tile: nact = ceil(tile_end / SLEN).
// grid = B*T*H/256 blocks.
// ---------------------------------------------------------------------------
__global__ __launch_bounds__(256) void reduce_kernel(float* __restrict__ out)
{
    const int idx = blockIdx.x * 256 + threadIdx.x;   // over B*T*H = 4M
    const int h = idx & (HH - 1);
    const int t = (idx >> 7) & (TT - 1);
    const int b = idx >> 18;

    const int tile_end = ((t >> 7) + 1) << 7;         // (t/128+1)*128
    const int nact = (tile_end + SLEN - 1) / SLEN;

    float sum = 0.0f;
    const size_t off = (size_t)b * TT * HH + (size_t)t * HH + h;
    #pragma unroll 4
    for (int j = 0; j < nact; j++)
        sum += g_part[(size_t)j * BB * TT * HH + off];
    out[idx] = sum;
}

extern "C" void kernel_launch(void* const* d_in, const int* in_sizes, int n_in,
                              void* d_out, int out_size)
{
    const float* x  = (const float*)d_in[0];
    const float* Wq = (const float*)d_in[1];
    const float* Wk = (const float*)d_in[2];
    const float* Wv = (const float*)d_in[3];
    float* out = (float*)d_out;

    qkv_kernel<<<dim3((BB * TT) / 64, 3), 256>>>(x, Wq, Wk, Wv);
    st_kernel<<<dim3(TT / 128, TT / 128, BB), 256>>>();
    stats_kernel<<<dim3(TT, BB), 256>>>();
    out_kernel<<<dim3(TT / 128, NS, BB), 256>>>();
    reduce_kernel<<<(BB * TT * HH) / 256, 256>>>(out);
}

// round 4
// speedup vs baseline: 2.3735x; 1.8074x over previous
#include <cuda_runtime.h>
#include <cuda_bf16.h>
#include <math.h>
#include <stdint.h>

#define BB 4
#define TT 2048
#define CC 1024
#define HH 128
#define SCALE 0.08838834764831845f  // 1/sqrt(128)

#define NS   8     // split-K segments for out_kernel
#define SLEN 256   // keys per segment

#define PAD  40    // smem row stride in bf16 (80B: conflict-free ldmatrix)

// ---------------------------------------------------------------------------
// Device-global scratch
// ---------------------------------------------------------------------------
__device__ float g_v[BB * TT * HH];
__device__ __nv_bfloat16 g_qhi[BB * TT * HH];
__device__ __nv_bfloat16 g_qlo[BB * TT * HH];
__device__ __nv_bfloat16 g_khi[BB * TT * HH];
__device__ __nv_bfloat16 g_klo[BB * TT * HH];
__device__ __nv_bfloat16 g_xhi[(size_t)BB * TT * CC];
__device__ __nv_bfloat16 g_xlo[(size_t)BB * TT * CC];
__device__ __nv_bfloat16 g_wthi[3 * HH * CC];   // [y][n][k] = W[k][n]
__device__ __nv_bfloat16 g_wtlo[3 * HH * CC];
__device__ float g_st[(size_t)BB * TT * TT];
__device__ float g_m[BB * TT];
__device__ float g_rd[BB * TT];
__device__ float g_part[(size_t)NS * BB * TT * HH];

// ---------------------------------------------------------------------------
// mma.sync / ldmatrix helpers (baseline PTX, works under compute_103)
// ---------------------------------------------------------------------------
__device__ __forceinline__ uint32_t smem_u32(const void* p) {
    uint32_t a;
    asm("{ .reg .u64 t; cvta.to.shared.u64 t, %1; cvt.u32.u64 %0, t; }"
        : "=r"(a) : "l"(p));
    return a;
}

__device__ __forceinline__ void ldsm4(uint32_t r[4], uint32_t addr) {
    asm volatile("ldmatrix.sync.aligned.m8n8.x4.shared.b16 {%0,%1,%2,%3}, [%4];"
                 : "=r"(r[0]), "=r"(r[1]), "=r"(r[2]), "=r"(r[3]) : "r"(addr));
}

__device__ __forceinline__ void mma16816(float d[4], const uint32_t a[4],
                                         uint32_t b0, uint32_t b1) {
    asm volatile(
        "mma.sync.aligned.m16n8k16.row.col.f32.bf16.bf16.f32 "
        "{%0,%1,%2,%3}, {%4,%5,%6,%7}, {%8,%9}, {%0,%1,%2,%3};"
        : "+f"(d[0]), "+f"(d[1]), "+f"(d[2]), "+f"(d[3])
        : "r"(a[0]), "r"(a[1]), "r"(a[2]), "r"(a[3]), "r"(b0), "r"(b1));
}

// Load one 128x32 bf16 tile (row-major, leading dim ld) into padded smem.
__device__ __forceinline__ void load_tile(const __nv_bfloat16* __restrict__ src,
                                          int ld, __nv_bfloat16* dst, int tid) {
    #pragma unroll
    for (int i = 0; i < 2; i++) {
        int v = tid + i * 256;        // 0..511
        int r = v >> 2, c = v & 3;    // row, 16B chunk
        *reinterpret_cast<uint4*>(dst + r * PAD + c * 8) =
            *reinterpret_cast<const uint4*>(src + (size_t)r * ld + c * 8);
    }
}

// smem byte offsets (bf16 tile = 128*PAD = 5120 elems = 10240 B)
#define OFF_AHI 0u
#define OFF_ALO 10240u
#define OFF_BHI 20480u
#define OFF_BLO 30720u

// One K=32 chunk: 2 k-steps of 16; per step load frags and do hh+lh+hl.
__device__ __forceinline__ void gemm_chunk(uint32_t sbase, int lane, int wm, int wn,
                                           float acc[4][4][4]) {
    #pragma unroll
    for (int ks = 0; ks < 2; ks++) {
        const int k0 = ks * 16;
        uint32_t a_hi[4][4], a_lo[4][4], b_hi[2][4], b_lo[2][4];

        const int arow = lane & 15;
        const int acol = k0 + ((lane >> 4) << 3);
        #pragma unroll
        for (int i = 0; i < 4; i++) {
            uint32_t off = (uint32_t)((wm * 64 + i * 16 + arow) * PAD + acol) * 2;
            ldsm4(a_hi[i], sbase + OFF_AHI + off);
            ldsm4(a_lo[i], sbase + OFF_ALO + off);
        }

        const int brow = (lane & 7) + ((lane >> 4) << 3);
        const int bcol = k0 + ((lane >> 3) & 1) * 8;
        #pragma unroll
        for (int j = 0; j < 2; j++) {
            uint32_t off = (uint32_t)((wn * 32 + j * 16 + brow) * PAD + bcol) * 2;
            ldsm4(b_hi[j], sbase + OFF_BHI + off);
            ldsm4(b_lo[j], sbase + OFF_BLO + off);
        }

        #pragma unroll
        for (int i = 0; i < 4; i++) {
            #pragma unroll
            for (int jn = 0; jn < 4; jn++) {
                uint32_t b0h = b_hi[jn >> 1][(jn & 1) * 2];
                uint32_t b1h = b_hi[jn >> 1][(jn & 1) * 2 + 1];
                uint32_t b0l = b_lo[jn >> 1][(jn & 1) * 2];
                uint32_t b1l = b_lo[jn >> 1][(jn & 1) * 2 + 1];
                mma16816(acc[i][jn], a_hi[i], b0h, b1h);   // hh
                mma16816(acc[i][jn], a_lo[i], b0h, b1h);   // lh
                mma16816(acc[i][jn], a_hi[i], b0l, b1l);   // hl
            }
        }
    }
}

// ---------------------------------------------------------------------------
// P0a: split x into bf16 hi/lo
// ---------------------------------------------------------------------------
__global__ __launch_bounds__(256) void prep_x_kernel(const float* __restrict__ x)
{
    size_t i = (size_t)blockIdx.x * 256 + threadIdx.x;
    float f = x[i];
    __nv_bfloat16 hi = __float2bfloat16(f);
    g_xhi[i] = hi;
    g_xlo[i] = __float2bfloat16(f - __bfloat162float(hi));
}

// ---------------------------------------------------------------------------
// P0b: transpose + split W
// ---------------------------------------------------------------------------
__global__ __launch_bounds__(256) void prep_w_kernel(
    const float* __restrict__ Wq, const float* __restrict__ Wk, const float* __restrict__ Wv)
{
    int i = blockIdx.x * 256 + threadIdx.x;      // 3*128*1024
    int k = i & (CC - 1);
    int n = (i >> 10) & (HH - 1);
    int y = i >> 17;
    const float* W = (y == 0) ? Wq : (y == 1) ? Wk : Wv;
    float f = W[(size_t)k * HH + n];
    __nv_bfloat16 hi = __float2bfloat16(f);
    g_wthi[i] = hi;
    g_wtlo[i] = __float2bfloat16(f - __bfloat162float(hi));
}

// ---------------------------------------------------------------------------
// K1: QKV projection via mma.sync. 128x128 CTA tile, 8 warps of 64x32.
// grid = (B*T/128, 3), 256 threads.
// ---------------------------------------------------------------------------
__global__ __launch_bounds__(256) void qkv_mma_kernel()
{
    __shared__ __align__(16) __nv_bfloat16 smem[4 * 128 * PAD];

    const int tid  = threadIdx.x;
    const int wid  = tid >> 5;
    const int lane = tid & 31;
    const int wm   = wid & 1;       // 0..1 (m)
    const int wn   = wid >> 1;      // 0..3 (n)
    const int y    = blockIdx.y;
    const int row0 = blockIdx.x * 128;
    const uint32_t sbase = smem_u32(smem);

    const __nv_bfloat16* Ahi = g_xhi + (size_t)row0 * CC;
    const __nv_bfloat16* Alo = g_xlo + (size_t)row0 * CC;
    const __nv_bfloat16* Bhi = g_wthi + (size_t)y * HH * CC;
    const __nv_bfloat16* Blo = g_wtlo + (size_t)y * HH * CC;

    float acc[4][4][4] = {};

    for (int kc = 0; kc < CC / 32; kc++) {
        const int k0 = kc * 32;
        load_tile(Ahi + k0, CC, smem,                   tid);
        load_tile(Alo + k0, CC, smem + 128 * PAD,       tid);
        load_tile(Bhi + k0, CC, smem + 2 * 128 * PAD,   tid);
        load_tile(Blo + k0, CC, smem + 3 * 128 * PAD,   tid);
        __syncthreads();
        gemm_chunk(sbase, lane, wm, wn, acc);
        __syncthreads();
    }

    const int g  = lane >> 2;
    const int c2 = (lane & 3) * 2;
    #pragma unroll
    for (int i = 0; i < 4; i++) {
        #pragma unroll
        for (int jn = 0; jn < 4; jn++) {
            int m = row0 + wm * 64 + i * 16 + g;
            int n = wn * 32 + jn * 8 + c2;
            #pragma unroll
            for (int e = 0; e < 4; e++) {
                int mm = m + (e >> 1) * 8;
                int nn = n + (e & 1);
                float fv = acc[i][jn][e];
                size_t o = (size_t)mm * HH + nn;
                if (y == 2) {
                    g_v[o] = fv;
                } else {
                    __nv_bfloat16 hi = __float2bfloat16(fv);
                    __nv_bfloat16 lo = __float2bfloat16(fv - __bfloat162float(hi));
                    if (y == 0) { g_qhi[o] = hi; g_qlo[o] = lo; }
                    else        { g_khi[o] = hi; g_klo[o] = lo; }
                }
            }
        }
    }
}

// ---------------------------------------------------------------------------
// K2: ST[b][s][t] = scale*k[s].q[t] (t>=s else -inf), causal tiles only.
// A = k rows (s), B = q rows (t). K = 128 in 4 chunks.
// grid = (T/128 t-tiles, T/128 s-tiles, B).
// ---------------------------------------------------------------------------
__global__ __launch_bounds__(256) void st_mma_kernel()
{
    const int b  = blockIdx.z;
    const int t0 = blockIdx.x * 128;
    const int s0 = blockIdx.y * 128;
    if (t0 + 127 < s0) return;   // fully masked tile: never written, never read

    __shared__ __align__(16) __nv_bfloat16 smem[4 * 128 * PAD];

    const int tid  = threadIdx.x;
    const int wid  = tid >> 5;
    const int lane = tid & 31;
    const int wm   = wid & 1;
    const int wn   = wid >> 1;
    const uint32_t sbase = smem_u32(smem);

    const __nv_bfloat16* Ahi = g_khi + ((size_t)b * TT + s0) * HH;
    const __nv_bfloat16* Alo = g_klo + ((size_t)b * TT + s0) * HH;
    const __nv_bfloat16* Bhi = g_qhi + ((size_t)b * TT + t0) * HH;
    const __nv_bfloat16* Blo = g_qlo + ((size_t)b * TT + t0) * HH;

    float acc[4][4][4] = {};

    for (int kc = 0; kc < HH / 32; kc++) {
        const int k0 = kc * 32;
        load_tile(Ahi + k0, HH, smem,                   tid);
        load_tile(Alo + k0, HH, smem + 128 * PAD,       tid);
        load_tile(Bhi + k0, HH, smem + 2 * 128 * PAD,   tid);
        load_tile(Blo + k0, HH, smem + 3 * 128 * PAD,   tid);
        __syncthreads();
        gemm_chunk(sbase, lane, wm, wn, acc);
        __syncthreads();
    }

    float* stb = g_st + (size_t)b * TT * TT;
    const int g  = lane >> 2;
    const int c2 = (lane & 3) * 2;
    #pragma unroll
    for (int i = 0; i < 4; i++) {
        #pragma unroll
        for (int jn = 0; jn < 4; jn++) {
            int s = s0 + wm * 64 + i * 16 + g;
            int t = t0 + wn * 32 + jn * 8 + c2;
            #pragma unroll
            for (int e = 0; e < 4; e++) {
                int ss = s + (e >> 1) * 8;
                int tt = t + (e & 1);
                stb[(size_t)ss * TT + tt] =
                    (tt >= ss) ? acc[i][jn][e] * SCALE : -INFINITY;
            }
        }
    }
}

// ---------------------------------------------------------------------------
// K3: per-(b,s) column stats over t in [s, T): max and 1/sum(exp).
// ---------------------------------------------------------------------------
__global__ __launch_bounds__(256) void stats_kernel()
{
    const int s = blockIdx.x;
    const int b = blockIdx.y;
    const float* row = g_st + (size_t)b * TT * TT + (size_t)s * TT;
    const int tid = threadIdx.x;

    __shared__ float red[256];

    float m = -INFINITY;
    for (int t = s + tid; t < TT; t += 256) m = fmaxf(m, row[t]);
    red[tid] = m;
    __syncthreads();
    for (int off = 128; off > 0; off >>= 1) {
        if (tid < off) red[tid] = fmaxf(red[tid], red[tid + off]);
        __syncthreads();
    }
    const float mv = red[0];
    __syncthreads();

    float d = 0.0f;
    for (int t = s + tid; t < TT; t += 256) d += __expf(row[t] - mv);
    red[tid] = d;
    __syncthreads();
    for (int off = 128; off > 0; off >>= 1) {
        if (tid < off) red[tid] += red[tid + off];
        __syncthreads();
    }
    if (tid == 0) {
        g_m[b * TT + s]  = mv;
        g_rd[b * TT + s] = 1.0f / red[0];
    }
}

// ---------------------------------------------------------------------------
// K4: split-K out partials (round-2 known-good)
// ---------------------------------------------------------------------------
__global__ __launch_bounds__(256) void out_kernel()
{
    const int b  = blockIdx.z;
    const int t0 = blockIdx.x * 128;
    const int js = blockIdx.y;

    const int s_begin = js * SLEN;
    const int s_end_v = (js + 1) * SLEN;
    const int s_end   = (s_end_v < t0 + 128) ? s_end_v : (t0 + 128);
    if (s_begin >= s_end) return;

    const float* stb = g_st + (size_t)b * TT * TT;
    const float* vp  = g_v + (size_t)b * TT * HH;
    const float* mp  = g_m + b * TT;
    const float* rdp = g_rd + b * TT;
    float* part = g_part + ((size_t)js * BB + b) * TT * HH;

    const int tid = threadIdx.x;
    const int ty  = tid >> 4;
    const int tx  = tid & 15;

    __shared__ float Ps[32][128];
    __shared__ float Vs[32][128];

    float acc[8][8] = {};

    for (int sc = s_begin; sc < s_end; sc += 32) {
        #pragma unroll
        for (int i = 0; i < 16; i++) {
            int idx = tid + i * 256;
            int ss = idx >> 7, ttl = idx & 127;
            int s = sc + ss;
            float val = stb[(size_t)s * TT + t0 + ttl];
            Ps[ss][ttl] = __expf(val - mp[s]) * rdp[s];
        }
        #pragma unroll
        for (int i = 0; i < 16; i++) {
            int idx = tid + i * 256;
            int ss = idx >> 7, h = idx & 127;
            Vs[ss][h] = vp[(size_t)(sc + ss) * HH + h];
        }
        __syncthreads();

        #pragma unroll
        for (int kk = 0; kk < 32; kk++) {
            float a[8], bb[8];
            #pragma unroll
            for (int i = 0; i < 8; i++) a[i] = Ps[kk][ty * 8 + i];
            #pragma unroll
            for (int j = 0; j < 8; j++) bb[j] = Vs[kk][tx * 8 + j];
            #pragma unroll
            for (int i = 0; i < 8; i++)
                #pragma unroll
                for (int j = 0; j < 8; j++)
                    acc[i][j] += a[i] * bb[j];
        }
        __syncthreads();
    }

    #pragma unroll
    for (int i = 0; i < 8; i++)
        #pragma unroll
        for (int j = 0; j < 8; j++)
            part[(size_t)(t0 + ty * 8 + i) * HH + tx * 8 + j] = acc[i][j];
}

// ---------------------------------------------------------------------------
// K5: reduce partials -> out
// ---------------------------------------------------------------------------
__global__ __launch_bounds__(256) void reduce_kernel(float* __restrict__ out)
{
    const int idx = blockIdx.x * 256 + threadIdx.x;
    const int h = idx & (HH - 1);
    const int t = (idx >> 7) & (TT - 1);
    const int b = idx >> 18;

    const int tile_end = ((t >> 7) + 1) << 7;
    const int nact = (tile_end + SLEN - 1) / SLEN;

    float sum = 0.0f;
    const size_t off = (size_t)b * TT * HH + (size_t)t * HH + h;
    #pragma unroll 4
    for (int j = 0; j < nact; j++)
        sum += g_part[(size_t)j * BB * TT * HH + off];
    out[idx] = sum;
}

extern "C" void kernel_launch(void* const* d_in, const int* in_sizes, int n_in,
                              void* d_out, int out_size)
{
    const float* x  = (const float*)d_in[0];
    const float* Wq = (const float*)d_in[1];
    const float* Wk = (const float*)d_in[2];
    const float* Wv = (const float*)d_in[3];
    float* out = (float*)d_out;

    prep_x_kernel<<<(BB * TT * CC) / 256, 256>>>(x);
    prep_w_kernel<<<(3 * HH * CC) / 256, 256>>>(Wq, Wk, Wv);
    qkv_mma_kernel<<<dim3((BB * TT) / 128, 3), 256>>>();
    st_mma_kernel<<<dim3(TT / 128, TT / 128, BB), 256>>>();
    stats_kernel<<<dim3(TT, BB), 256>>>();
    out_kernel<<<dim3(TT / 128, NS, BB), 256>>>();
    reduce_kernel<<<(BB * TT * HH) / 256, 256>>>(out);
}

// round 6
// speedup vs baseline: 2.7882x; 1.1748x over previous
#include <cuda_runtime.h>
#include <cuda_bf16.h>
#include <math.h>
#include <stdint.h>

#define BB 4
#define TT 2048
#define CC 1024
#define HH 128
#define SCALE 0.08838834764831845f  // 1/sqrt(128)

#define NS   8     // split-K segments for out_kernel
#define SLEN 256   // keys per segment

#define PAD  40    // smem row stride (bf16) for K-chunk-32 GEMM tiles
#define PADT 136   // smem row stride (bf16) for 128-wide transposed tiles

// ---------------------------------------------------------------------------
// Device-global scratch
// ---------------------------------------------------------------------------
__device__ __nv_bfloat16 g_vhi[BB * TT * HH];
__device__ __nv_bfloat16 g_vlo[BB * TT * HH];
__device__ __nv_bfloat16 g_qhi[BB * TT * HH];
__device__ __nv_bfloat16 g_qlo[BB * TT * HH];
__device__ __nv_bfloat16 g_khi[BB * TT * HH];
__device__ __nv_bfloat16 g_klo[BB * TT * HH];
__device__ __nv_bfloat16 g_xhi[(size_t)BB * TT * CC];
__device__ __nv_bfloat16 g_xlo[(size_t)BB * TT * CC];
__device__ __nv_bfloat16 g_wthi[3 * HH * CC];   // [y][n][k] = W[k][n]
__device__ __nv_bfloat16 g_wtlo[3 * HH * CC];
__device__ float g_st[(size_t)BB * TT * TT];
__device__ float g_m[BB * TT];
__device__ float g_rd[BB * TT];
__device__ float g_part[(size_t)NS * BB * TT * HH];

// ---------------------------------------------------------------------------
// mma.sync / ldmatrix helpers (baseline PTX, works under compute_103)
// ---------------------------------------------------------------------------
__device__ __forceinline__ uint32_t smem_u32(const void* p) {
    uint32_t a;
    asm("{ .reg .u64 t; cvta.to.shared.u64 t, %1; cvt.u32.u64 %0, t; }"
        : "=r"(a) : "l"(p));
    return a;
}

__device__ __forceinline__ void ldsm4(uint32_t r[4], uint32_t addr) {
    asm volatile("ldmatrix.sync.aligned.m8n8.x4.shared.b16 {%0,%1,%2,%3}, [%4];"
                 : "=r"(r[0]), "=r"(r[1]), "=r"(r[2]), "=r"(r[3]) : "r"(addr));
}

__device__ __forceinline__ void ldsm4t(uint32_t r[4], uint32_t addr) {
    asm volatile("ldmatrix.sync.aligned.m8n8.x4.trans.shared.b16 {%0,%1,%2,%3}, [%4];"
                 : "=r"(r[0]), "=r"(r[1]), "=r"(r[2]), "=r"(r[3]) : "r"(addr));
}

__device__ __forceinline__ void mma16816(float d[4], const uint32_t a[4],
                                         uint32_t b0, uint32_t b1) {
    asm volatile(
        "mma.sync.aligned.m16n8k16.row.col.f32.bf16.bf16.f32 "
        "{%0,%1,%2,%3}, {%4,%5,%6,%7}, {%8,%9}, {%0,%1,%2,%3};"
        : "+f"(d[0]), "+f"(d[1]), "+f"(d[2]), "+f"(d[3])
        : "r"(a[0]), "r"(a[1]), "r"(a[2]), "r"(a[3]), "r"(b0), "r"(b1));
}

// Load one 128x32 bf16 tile (row-major, leading dim ld) into padded smem.
__device__ __forceinline__ void load_tile(const __nv_bfloat16* __restrict__ src,
                                          int ld, __nv_bfloat16* dst, int tid) {
    #pragma unroll
    for (int i = 0; i < 2; i++) {
        int v = tid + i * 256;        // 0..511
        int r = v >> 2, c = v & 3;    // row, 16B chunk
        *reinterpret_cast<uint4*>(dst + r * PAD + c * 8) =
            *reinterpret_cast<const uint4*>(src + (size_t)r * ld + c * 8);
    }
}

// One K=32 chunk (non-trans, A [m][k], B [n][k], both padded PAD).
__device__ __forceinline__ void gemm_chunk(uint32_t sbase, int lane, int wm, int wn,
                                           float acc[4][4][4]) {
    #pragma unroll
    for (int ks = 0; ks < 2; ks++) {
        const int k0 = ks * 16;
        uint32_t a_hi[4][4], a_lo[4][4], b_hi[2][4], b_lo[2][4];

        const int arow = lane & 15;
        const int acol = k0 + ((lane >> 4) << 3);
        #pragma unroll
        for (int i = 0; i < 4; i++) {
            uint32_t off = (uint32_t)((wm * 64 + i * 16 + arow) * PAD + acol) * 2;
            ldsm4(a_hi[i], sbase + off);
            ldsm4(a_lo[i], sbase + 10240u + off);
        }

        const int brow = (lane & 7) + ((lane >> 4) << 3);
        const int bcol = k0 + ((lane >> 3) & 1) * 8;
        #pragma unroll
        for (int j = 0; j < 2; j++) {
            uint32_t off = (uint32_t)((wn * 32 + j * 16 + brow) * PAD + bcol) * 2;
            ldsm4(b_hi[j], sbase + 20480u + off);
            ldsm4(b_lo[j], sbase + 30720u + off);
        }

        #pragma unroll
        for (int i = 0; i < 4; i++) {
            #pragma unroll
            for (int jn = 0; jn < 4; jn++) {
                uint32_t b0h = b_hi[jn >> 1][(jn & 1) * 2];
                uint32_t b1h = b_hi[jn >> 1][(jn & 1) * 2 + 1];
                uint32_t b0l = b_lo[jn >> 1][(jn & 1) * 2];
                uint32_t b1l = b_lo[jn >> 1][(jn & 1) * 2 + 1];
                mma16816(acc[i][jn], a_hi[i], b0h, b1h);   // hh
                mma16816(acc[i][jn], a_lo[i], b0h, b1h);   // lh
                mma16816(acc[i][jn], a_hi[i], b0l, b1l);   // hl
            }
        }
    }
}

// ---------------------------------------------------------------------------
// P0a: split x into bf16 hi/lo
// ---------------------------------------------------------------------------
__global__ __launch_bounds__(256) void prep_x_kernel(const float* __restrict__ x)
{
    size_t i = (size_t)blockIdx.x * 256 + threadIdx.x;
    float f = x[i];
    __nv_bfloat16 hi = __float2bfloat16(f);
    g_xhi[i] = hi;
    g_xlo[i] = __float2bfloat16(f - __bfloat162float(hi));
}

// ---------------------------------------------------------------------------
// P0b: transpose + split W
// ---------------------------------------------------------------------------
__global__ __launch_bounds__(256) void prep_w_kernel(
    const float* __restrict__ Wq, const float* __restrict__ Wk, const float* __restrict__ Wv)
{
    int i = blockIdx.x * 256 + threadIdx.x;      // 3*128*1024
    int k = i & (CC - 1);
    int n = (i >> 10) & (HH - 1);
    int y = i >> 17;
    const float* W = (y == 0) ? Wq : (y == 1) ? Wk : Wv;
    float f = W[(size_t)k * HH + n];
    __nv_bfloat16 hi = __float2bfloat16(f);
    g_wthi[i] = hi;
    g_wtlo[i] = __float2bfloat16(f - __bfloat162float(hi));
}

// ---------------------------------------------------------------------------
// K1: QKV projection via mma.sync. 128x128 CTA tile, 8 warps of 64x32.
// grid = (B*T/128, 3), 256 threads.
// ---------------------------------------------------------------------------
__global__ __launch_bounds__(256) void qkv_mma_kernel()
{
    __shared__ __align__(16) __nv_bfloat16 smem[4 * 128 * PAD];

    const int tid  = threadIdx.x;
    const int wid  = tid >> 5;
    const int lane = tid & 31;
    const int wm   = wid & 1;
    const int wn   = wid >> 1;
    const int y    = blockIdx.y;
    const int row0 = blockIdx.x * 128;
    const uint32_t sbase = smem_u32(smem);

    const __nv_bfloat16* Ahi = g_xhi + (size_t)row0 * CC;
    const __nv_bfloat16* Alo = g_xlo + (size_t)row0 * CC;
    const __nv_bfloat16* Bhi = g_wthi + (size_t)y * HH * CC;
    const __nv_bfloat16* Blo = g_wtlo + (size_t)y * HH * CC;

    float acc[4][4][4] = {};

    for (int kc = 0; kc < CC / 32; kc++) {
        const int k0 = kc * 32;
        load_tile(Ahi + k0, CC, smem,                 tid);
        load_tile(Alo + k0, CC, smem + 128 * PAD,     tid);
        load_tile(Bhi + k0, CC, smem + 2 * 128 * PAD, tid);
        load_tile(Blo + k0, CC, smem + 3 * 128 * PAD, tid);
        __syncthreads();
        gemm_chunk(sbase, lane, wm, wn, acc);
        __syncthreads();
    }

    const int g  = lane >> 2;
    const int c2 = (lane & 3) * 2;
    #pragma unroll
    for (int i = 0; i < 4; i++) {
        #pragma unroll
        for (int jn = 0; jn < 4; jn++) {
            int m = row0 + wm * 64 + i * 16 + g;
            int n = wn * 32 + jn * 8 + c2;
            #pragma unroll
            for (int e = 0; e < 4; e++) {
                int mm = m + (e >> 1) * 8;
                int nn = n + (e & 1);
                float fv = acc[i][jn][e];
                size_t o = (size_t)mm * HH + nn;
                __nv_bfloat16 hi = __float2bfloat16(fv);
                __nv_bfloat16 lo = __float2bfloat16(fv - __bfloat162float(hi));
                if (y == 0)      { g_qhi[o] = hi; g_qlo[o] = lo; }
                else if (y == 1) { g_khi[o] = hi; g_klo[o] = lo; }
                else             { g_vhi[o] = hi; g_vlo[o] = lo; }
            }
        }
    }
}

// ---------------------------------------------------------------------------
// K2: ST[b][s][t] = scale*k[s].q[t] (t>=s else -inf), causal tiles only.
// grid = (T/128 t-tiles, T/128 s-tiles, B).
// ---------------------------------------------------------------------------
__global__ __launch_bounds__(256) void st_mma_kernel()
{
    const int b  = blockIdx.z;
    const int t0 = blockIdx.x * 128;
    const int s0 = blockIdx.y * 128;
    if (t0 + 127 < s0) return;

    __shared__ __align__(16) __nv_bfloat16 smem[4 * 128 * PAD];

    const int tid  = threadIdx.x;
    const int wid  = tid >> 5;
    const int lane = tid & 31;
    const int wm   = wid & 1;
    const int wn   = wid >> 1;
    const uint32_t sbase = smem_u32(smem);

    const __nv_bfloat16* Ahi = g_khi + ((size_t)b * TT + s0) * HH;
    const __nv_bfloat16* Alo = g_klo + ((size_t)b * TT + s0) * HH;
    const __nv_bfloat16* Bhi = g_qhi + ((size_t)b * TT + t0) * HH;
    const __nv_bfloat16* Blo = g_qlo + ((size_t)b * TT + t0) * HH;

    float acc[4][4][4] = {};

    for (int kc = 0; kc < HH / 32; kc++) {
        const int k0 = kc * 32;
        load_tile(Ahi + k0, HH, smem,                 tid);
        load_tile(Alo + k0, HH, smem + 128 * PAD,     tid);
        load_tile(Bhi + k0, HH, smem + 2 * 128 * PAD, tid);
        load_tile(Blo + k0, HH, smem + 3 * 128 * PAD, tid);
        __syncthreads();
        gemm_chunk(sbase, lane, wm, wn, acc);
        __syncthreads();
    }

    float* stb = g_st + (size_t)b * TT * TT;
    const int g  = lane >> 2;
    const int c2 = (lane & 3) * 2;
    #pragma unroll
    for (int i = 0; i < 4; i++) {
        #pragma unroll
        for (int jn = 0; jn < 4; jn++) {
            int s = s0 + wm * 64 + i * 16 + g;
            int t = t0 + wn * 32 + jn * 8 + c2;
            #pragma unroll
            for (int e = 0; e < 4; e++) {
                int ss = s + (e >> 1) * 8;
                int tt = t + (e & 1);
                stb[(size_t)ss * TT + tt] =
                    (tt >= ss) ? acc[i][jn][e] * SCALE : -INFINITY;
            }
        }
    }
}

// ---------------------------------------------------------------------------
// K3: single-pass online softmax stats per (b,s) over t in [s, T).
// m initialized to -1e30 (NOT -inf): empty partials merge as
// d*exp(-1e30 - (-1e30)) = d*exp(0), avoiding inf-inf = NaN.
// ---------------------------------------------------------------------------
__global__ __launch_bounds__(256) void stats_kernel()
{
    const int s = blockIdx.x;
    const int b = blockIdx.y;
    const float* row = g_st + (size_t)b * TT * TT + (size_t)s * TT;
    const int tid = threadIdx.x;

    __shared__ float rm[256], rdn[256];

    float m = -1e30f, d = 0.0f;
    for (int t = s + tid; t < TT; t += 256) {
        float v = row[t];
        float mn = fmaxf(m, v);
        d = d * __expf(m - mn) + __expf(v - mn);
        m = mn;
    }
    rm[tid] = m; rdn[tid] = d;
    __syncthreads();
    for (int off = 128; off > 0; off >>= 1) {
        if (tid < off) {
            float m2 = rm[tid + off], d2 = rdn[tid + off];
            float mn = fmaxf(rm[tid], m2);
            rdn[tid] = rdn[tid] * __expf(rm[tid] - mn) + d2 * __expf(m2 - mn);
            rm[tid] = mn;
        }
        __syncthreads();
    }
    if (tid == 0) {
        g_m[b * TT + s]  = rm[0];
        g_rd[b * TT + s] = 1.0f / rdn[0];
    }
}

// ---------------------------------------------------------------------------
// K4: split-K out partials via mma.sync + ldmatrix.trans.
// part[t][h] += sum_{s in seg} P[s][t]*v[s][h].
// grid = (T/128, NS, B).
// ---------------------------------------------------------------------------
__global__ __launch_bounds__(256) void out_mma_kernel()
{
    const int b  = blockIdx.z;
    const int t0 = blockIdx.x * 128;
    const int js = blockIdx.y;

    const int s_begin = js * SLEN;
    const int s_end_v = (js + 1) * SLEN;
    const int s_end   = (s_end_v < t0 + 128) ? s_end_v : (t0 + 128);
    if (s_begin >= s_end) return;

    __shared__ __align__(16) __nv_bfloat16 smem[4 * 32 * PADT];  // Phi|Plo|Vhi|Vlo

    const float* stb = g_st + (size_t)b * TT * TT;
    const __nv_bfloat16* vhi = g_vhi + (size_t)b * TT * HH;
    const __nv_bfloat16* vlo = g_vlo + (size_t)b * TT * HH;
    const float* mp  = g_m + b * TT;
    const float* rdp = g_rd + b * TT;
    float* part = g_part + ((size_t)js * BB + b) * TT * HH;

    const int tid  = threadIdx.x;
    const int wid  = tid >> 5;
    const int lane = tid & 31;
    const int wm   = wid & 1;    // t-half
    const int wn   = wid >> 1;   // h-quarter
    const uint32_t sbase = smem_u32(smem);
    const uint32_t OPHI = 0u, OPLO = 32u * PADT * 2u,
                   OVHI = 64u * PADT * 2u, OVLO = 96u * PADT * 2u;

    float acc[4][4][4] = {};

    for (int sc = s_begin; sc < s_end; sc += 32) {
        // P chunk: compute softmax probs, split to hi/lo, store [s][t]
        #pragma unroll
        for (int i = 0; i < 16; i++) {
            int idx = tid + i * 256;
            int ss = idx >> 7, ttl = idx & 127;
            int s = sc + ss;
            float val = stb[(size_t)s * TT + t0 + ttl];
            float p = __expf(val - mp[s]) * rdp[s];    // exp(-inf)=0 masks
            __nv_bfloat16 hi = __float2bfloat16(p);
            __nv_bfloat16 lo = __float2bfloat16(p - __bfloat162float(hi));
            smem[ss * PADT + ttl] = hi;
            smem[32 * PADT + ss * PADT + ttl] = lo;
        }
        // V chunk [s][h], vectorized
        #pragma unroll
        for (int i = 0; i < 2; i++) {
            int v = tid + i * 256;          // 0..511
            int r = v >> 4, c = v & 15;     // row 0..31, 8-elem chunk
            *reinterpret_cast<uint4*>(smem + 64 * PADT + r * PADT + c * 8) =
                *reinterpret_cast<const uint4*>(vhi + (size_t)(sc + r) * HH + c * 8);
            *reinterpret_cast<uint4*>(smem + 96 * PADT + r * PADT + c * 8) =
                *reinterpret_cast<const uint4*>(vlo + (size_t)(sc + r) * HH + c * 8);
        }
        __syncthreads();

        #pragma unroll
        for (int ks = 0; ks < 2; ks++) {
            const int k0 = ks * 16;
            uint32_t a_hi[4][4], a_lo[4][4], b_hi[2][4], b_lo[2][4];

            // A = P^T via trans
            const int arow = k0 + (lane & 7) + ((lane >> 4) << 3);
            const int acoff = ((lane >> 3) & 1) * 8;
            #pragma unroll
            for (int i = 0; i < 4; i++) {
                uint32_t off = (uint32_t)(arow * PADT + wm * 64 + i * 16 + acoff) * 2;
                ldsm4t(a_hi[i], sbase + OPHI + off);
                ldsm4t(a_lo[i], sbase + OPLO + off);
            }

            // B = V via trans
            const int brow = k0 + (lane & 7) + (((lane >> 3) & 1) << 3);
            const int bcoff = ((lane >> 4) << 3);
            #pragma unroll
            for (int j = 0; j < 2; j++) {
                uint32_t off = (uint32_t)(brow * PADT + wn * 32 + j * 16 + bcoff) * 2;
                ldsm4t(b_hi[j], sbase + OVHI + off);
                ldsm4t(b_lo[j], sbase + OVLO + off);
            }

            #pragma unroll
            for (int i = 0; i < 4; i++) {
                #pragma unroll
                for (int jn = 0; jn < 4; jn++) {
                    uint32_t b0h = b_hi[jn >> 1][(jn & 1) * 2];
                    uint32_t b1h = b_hi[jn >> 1][(jn & 1) * 2 + 1];
                    uint32_t b0l = b_lo[jn >> 1][(jn & 1) * 2];
                    uint32_t b1l = b_lo[jn >> 1][(jn & 1) * 2 + 1];
                    mma16816(acc[i][jn], a_hi[i], b0h, b1h);   // hh
                    mma16816(acc[i][jn], a_lo[i], b0h, b1h);   // lh
                    mma16816(acc[i][jn], a_hi[i], b0l, b1l);   // hl
                }
            }
        }
        __syncthreads();
    }

    const int g  = lane >> 2;
    const int c2 = (lane & 3) * 2;
    #pragma unroll
    for (int i = 0; i < 4; i++) {
        #pragma unroll
        for (int jn = 0; jn < 4; jn++) {
            int t = t0 + wm * 64 + i * 16 + g;
            int h = wn * 32 + jn * 8 + c2;
            #pragma unroll
            for (int e = 0; e < 4; e++) {
                int tt = t + (e >> 1) * 8;
                int hh = h + (e & 1);
                part[(size_t)tt * HH + hh] = acc[i][jn][e];
            }
        }
    }
}

// ---------------------------------------------------------------------------
// K5: reduce partials -> out
// ---------------------------------------------------------------------------
__global__ __launch_bounds__(256) void reduce_kernel(float* __restrict__ out)
{
    const int idx = blockIdx.x * 256 + threadIdx.x;
    const int h = idx & (HH - 1);
    const int t = (idx >> 7) & (TT - 1);
    const int b = idx >> 18;

    const int tile_end = ((t >> 7) + 1) << 7;
    const int nact = (tile_end + SLEN - 1) / SLEN;

    float sum = 0.0f;
    const size_t off = (size_t)b * TT * HH + (size_t)t * HH + h;
    #pragma unroll 4
    for (int j = 0; j < nact; j++)
        sum += g_part[(size_t)j * BB * TT * HH + off];
    out[idx] = sum;
}

extern "C" void kernel_launch(void* const* d_in, const int* in_sizes, int n_in,
                              void* d_out, int out_size)
{
    const float* x  = (const float*)d_in[0];
    const float* Wq = (const float*)d_in[1];
    const float* Wk = (const float*)d_in[2];
    const float* Wv = (const float*)d_in[3];
    float* out = (float*)d_out;

    prep_x_kernel<<<(BB * TT * CC) / 256, 256>>>(x);
    prep_w_kernel<<<(3 * HH * CC) / 256, 256>>>(Wq, Wk, Wv);
    qkv_mma_kernel<<<dim3((BB * TT) / 128, 3), 256>>>();
    st_mma_kernel<<<dim3(TT / 128, TT / 128, BB), 256>>>();
    stats_kernel<<<dim3(TT, BB), 256>>>();
    out_mma_kernel<<<dim3(TT / 128, NS, BB), 256>>>();
    reduce_kernel<<<(BB * TT * HH) / 256, 256>>>(out);
}

// round 7
// speedup vs baseline: 3.1886x; 1.1436x over previous
#include <cuda_runtime.h>
#include <cuda_bf16.h>
#include <math.h>
#include <stdint.h>

#define BB 4
#define TT 2048
#define CC 1024
#define HH 128
#define SCALE 0.08838834764831845f  // 1/sqrt(128)

#define NS   8     // split-K segments for out_kernel
#define SLEN 256   // keys per segment

#define PAD  40    // smem row stride (bf16), conflict-free for ldmatrix
#define PADT 136   // smem row stride (bf16) for 128-wide transposed tiles

#define TILE_B   10240u                 // one padded 128x32 bf16 tile
#define STAGE_B  (4u * TILE_B)          // A_hi|A_lo|B_hi|B_lo
#define SMEM_DYN (2u * STAGE_B)         // 2 pipeline stages = 81920 B

// ---------------------------------------------------------------------------
// Device-global scratch
// ---------------------------------------------------------------------------
__device__ __nv_bfloat16 g_vhi[BB * TT * HH];
__device__ __nv_bfloat16 g_vlo[BB * TT * HH];
__device__ __nv_bfloat16 g_qhi[BB * TT * HH];
__device__ __nv_bfloat16 g_qlo[BB * TT * HH];
__device__ __nv_bfloat16 g_khi[BB * TT * HH];
__device__ __nv_bfloat16 g_klo[BB * TT * HH];
__device__ __nv_bfloat16 g_xhi[(size_t)BB * TT * CC];
__device__ __nv_bfloat16 g_xlo[(size_t)BB * TT * CC];
__device__ __nv_bfloat16 g_wthi[3 * HH * CC];   // [y][n][k] = W[k][n]
__device__ __nv_bfloat16 g_wtlo[3 * HH * CC];
__device__ float g_st[(size_t)BB * TT * TT];
__device__ float g_m[BB * TT];
__device__ float g_rd[BB * TT];
__device__ float g_part[(size_t)NS * BB * TT * HH];

// ---------------------------------------------------------------------------
// PTX helpers (baseline sm_80-level PTX, compiles under compute_103)
// ---------------------------------------------------------------------------
__device__ __forceinline__ uint32_t smem_u32(const void* p) {
    uint32_t a;
    asm("{ .reg .u64 t; cvta.to.shared.u64 t, %1; cvt.u32.u64 %0, t; }"
        : "=r"(a) : "l"(p));
    return a;
}

__device__ __forceinline__ void ldsm4(uint32_t r[4], uint32_t addr) {
    asm volatile("ldmatrix.sync.aligned.m8n8.x4.shared.b16 {%0,%1,%2,%3}, [%4];"
                 : "=r"(r[0]), "=r"(r[1]), "=r"(r[2]), "=r"(r[3]) : "r"(addr));
}

__device__ __forceinline__ void ldsm4t(uint32_t r[4], uint32_t addr) {
    asm volatile("ldmatrix.sync.aligned.m8n8.x4.trans.shared.b16 {%0,%1,%2,%3}, [%4];"
                 : "=r"(r[0]), "=r"(r[1]), "=r"(r[2]), "=r"(r[3]) : "r"(addr));
}

__device__ __forceinline__ void mma16816(float d[4], const uint32_t a[4],
                                         uint32_t b0, uint32_t b1) {
    asm volatile(
        "mma.sync.aligned.m16n8k16.row.col.f32.bf16.bf16.f32 "
        "{%0,%1,%2,%3}, {%4,%5,%6,%7}, {%8,%9}, {%0,%1,%2,%3};"
        : "+f"(d[0]), "+f"(d[1]), "+f"(d[2]), "+f"(d[3])
        : "r"(a[0]), "r"(a[1]), "r"(a[2]), "r"(a[3]), "r"(b0), "r"(b1));
}

__device__ __forceinline__ void cp16(uint32_t saddr, const void* gptr) {
    asm volatile("cp.async.cg.shared.global [%0], [%1], 16;"
                 :: "r"(saddr), "l"(gptr));
}
#define CP_COMMIT() asm volatile("cp.async.commit_group;" ::: "memory")
#define CP_WAIT1()  asm volatile("cp.async.wait_group 1;" ::: "memory")
#define CP_WAIT0()  asm volatile("cp.async.wait_group 0;" ::: "memory")

// Async-load 4 tiles (A_hi|A_lo|B_hi|B_lo, each 128x32, leading dim ld) into
// one pipeline stage at smem address sb. 8 cp.async per thread.
__device__ __forceinline__ void load4_async(
    const __nv_bfloat16* __restrict__ Ahi, const __nv_bfloat16* __restrict__ Alo,
    const __nv_bfloat16* __restrict__ Bhi, const __nv_bfloat16* __restrict__ Blo,
    int ld, uint32_t sb, int tid)
{
    #pragma unroll
    for (int i = 0; i < 2; i++) {
        int v = tid + i * 256;        // 0..511
        int r = v >> 2, c = v & 3;    // row, 16B chunk
        uint32_t so = (uint32_t)(r * PAD + c * 8) * 2;
        size_t   go = (size_t)r * ld + c * 8;
        cp16(sb + so,              Ahi + go);
        cp16(sb + TILE_B + so,     Alo + go);
        cp16(sb + 2 * TILE_B + so, Bhi + go);
        cp16(sb + 3 * TILE_B + so, Blo + go);
    }
}

// One K=32 chunk (non-trans, A [m][k], B [n][k], both padded PAD) at stage sbase.
__device__ __forceinline__ void gemm_chunk(uint32_t sbase, int lane, int wm, int wn,
                                           float acc[4][4][4]) {
    #pragma unroll
    for (int ks = 0; ks < 2; ks++) {
        const int k0 = ks * 16;
        uint32_t a_hi[4][4], a_lo[4][4], b_hi[2][4], b_lo[2][4];

        const int arow = lane & 15;
        const int acol = k0 + ((lane >> 4) << 3);
        #pragma unroll
        for (int i = 0; i < 4; i++) {
            uint32_t off = (uint32_t)((wm * 64 + i * 16 + arow) * PAD + acol) * 2;
            ldsm4(a_hi[i], sbase + off);
            ldsm4(a_lo[i], sbase + TILE_B + off);
        }

        const int brow = (lane & 7) + ((lane >> 4) << 3);
        const int bcol = k0 + ((lane >> 3) & 1) * 8;
        #pragma unroll
        for (int j = 0; j < 2; j++) {
            uint32_t off = (uint32_t)((wn * 32 + j * 16 + brow) * PAD + bcol) * 2;
            ldsm4(b_hi[j], sbase + 2 * TILE_B + off);
            ldsm4(b_lo[j], sbase + 3 * TILE_B + off);
        }

        #pragma unroll
        for (int i = 0; i < 4; i++) {
            #pragma unroll
            for (int jn = 0; jn < 4; jn++) {
                uint32_t b0h = b_hi[jn >> 1][(jn & 1) * 2];
                uint32_t b1h = b_hi[jn >> 1][(jn & 1) * 2 + 1];
                uint32_t b0l = b_lo[jn >> 1][(jn & 1) * 2];
                uint32_t b1l = b_lo[jn >> 1][(jn & 1) * 2 + 1];
                mma16816(acc[i][jn], a_hi[i], b0h, b1h);   // hh
                mma16816(acc[i][jn], a_lo[i], b0h, b1h);   // lh
                mma16816(acc[i][jn], a_hi[i], b0l, b1l);   // hl
            }
        }
    }
}

// ---------------------------------------------------------------------------
// P0a: split x into bf16 hi/lo
// ---------------------------------------------------------------------------
__global__ __launch_bounds__(256) void prep_x_kernel(const float* __restrict__ x)
{
    size_t i = (size_t)blockIdx.x * 256 + threadIdx.x;
    float f = x[i];
    __nv_bfloat16 hi = __float2bfloat16(f);
    g_xhi[i] = hi;
    g_xlo[i] = __float2bfloat16(f - __bfloat162float(hi));
}

// ---------------------------------------------------------------------------
// P0b: transpose + split W
// ---------------------------------------------------------------------------
__global__ __launch_bounds__(256) void prep_w_kernel(
    const float* __restrict__ Wq, const float* __restrict__ Wk, const float* __restrict__ Wv)
{
    int i = blockIdx.x * 256 + threadIdx.x;      // 3*128*1024
    int k = i & (CC - 1);
    int n = (i >> 10) & (HH - 1);
    int y = i >> 17;
    const float* W = (y == 0) ? Wq : (y == 1) ? Wk : Wv;
    float f = W[(size_t)k * HH + n];
    __nv_bfloat16 hi = __float2bfloat16(f);
    g_wthi[i] = hi;
    g_wtlo[i] = __float2bfloat16(f - __bfloat162float(hi));
}

// ---------------------------------------------------------------------------
// K1: QKV projection, cp.async 2-stage pipelined mma.sync.
// grid = (B*T/128, 3), 256 threads, dynamic smem 80KB.
// ---------------------------------------------------------------------------
__global__ __launch_bounds__(256) void qkv_mma_kernel()
{
    extern __shared__ __align__(16) uint8_t dynsmem[];

    const int tid  = threadIdx.x;
    const int wid  = tid >> 5;
    const int lane = tid & 31;
    const int wm   = wid & 1;
    const int wn   = wid >> 1;
    const int y    = blockIdx.y;
    const int row0 = blockIdx.x * 128;
    const uint32_t sb0 = smem_u32(dynsmem);

    const __nv_bfloat16* Ahi = g_xhi + (size_t)row0 * CC;
    const __nv_bfloat16* Alo = g_xlo + (size_t)row0 * CC;
    const __nv_bfloat16* Bhi = g_wthi + (size_t)y * HH * CC;
    const __nv_bfloat16* Blo = g_wtlo + (size_t)y * HH * CC;

    float acc[4][4][4] = {};
    const int NC = CC / 32;

    load4_async(Ahi, Alo, Bhi, Blo, CC, sb0, tid);
    CP_COMMIT();

    for (int kc = 0; kc < NC; kc++) {
        if (kc + 1 < NC) {
            const int k1 = (kc + 1) * 32;
            load4_async(Ahi + k1, Alo + k1, Bhi + k1, Blo + k1, CC,
                        sb0 + ((kc + 1) & 1) * STAGE_B, tid);
            CP_COMMIT();
            CP_WAIT1();
        } else {
            CP_WAIT0();
        }
        __syncthreads();
        gemm_chunk(sb0 + (kc & 1) * STAGE_B, lane, wm, wn, acc);
        __syncthreads();
    }

    const int g  = lane >> 2;
    const int c2 = (lane & 3) * 2;
    #pragma unroll
    for (int i = 0; i < 4; i++) {
        #pragma unroll
        for (int jn = 0; jn < 4; jn++) {
            int m = row0 + wm * 64 + i * 16 + g;
            int n = wn * 32 + jn * 8 + c2;
            #pragma unroll
            for (int e = 0; e < 4; e++) {
                int mm = m + (e >> 1) * 8;
                int nn = n + (e & 1);
                float fv = acc[i][jn][e];
                size_t o = (size_t)mm * HH + nn;
                __nv_bfloat16 hi = __float2bfloat16(fv);
                __nv_bfloat16 lo = __float2bfloat16(fv - __bfloat162float(hi));
                if (y == 0)      { g_qhi[o] = hi; g_qlo[o] = lo; }
                else if (y == 1) { g_khi[o] = hi; g_klo[o] = lo; }
                else             { g_vhi[o] = hi; g_vlo[o] = lo; }
            }
        }
    }
}

// ---------------------------------------------------------------------------
// K2: ST[b][s][t] = scale*k[s].q[t] (t>=s else -inf), causal tiles only,
// cp.async 2-stage pipelined. grid = (T/128, T/128, B), dyn smem 80KB.
// ---------------------------------------------------------------------------
__global__ __launch_bounds__(256) void st_mma_kernel()
{
    const int b  = blockIdx.z;
    const int t0 = blockIdx.x * 128;
    const int s0 = blockIdx.y * 128;
    if (t0 + 127 < s0) return;

    extern __shared__ __align__(16) uint8_t dynsmem[];

    const int tid  = threadIdx.x;
    const int wid  = tid >> 5;
    const int lane = tid & 31;
    const int wm   = wid & 1;
    const int wn   = wid >> 1;
    const uint32_t sb0 = smem_u32(dynsmem);

    const __nv_bfloat16* Ahi = g_khi + ((size_t)b * TT + s0) * HH;
    const __nv_bfloat16* Alo = g_klo + ((size_t)b * TT + s0) * HH;
    const __nv_bfloat16* Bhi = g_qhi + ((size_t)b * TT + t0) * HH;
    const __nv_bfloat16* Blo = g_qlo + ((size_t)b * TT + t0) * HH;

    float acc[4][4][4] = {};
    const int NC = HH / 32;

    load4_async(Ahi, Alo, Bhi, Blo, HH, sb0, tid);
    CP_COMMIT();

    for (int kc = 0; kc < NC; kc++) {
        if (kc + 1 < NC) {
            const int k1 = (kc + 1) * 32;
            load4_async(Ahi + k1, Alo + k1, Bhi + k1, Blo + k1, HH,
                        sb0 + ((kc + 1) & 1) * STAGE_B, tid);
            CP_COMMIT();
            CP_WAIT1();
        } else {
            CP_WAIT0();
        }
        __syncthreads();
        gemm_chunk(sb0 + (kc & 1) * STAGE_B, lane, wm, wn, acc);
        __syncthreads();
    }

    float* stb = g_st + (size_t)b * TT * TT;
    const int g  = lane >> 2;
    const int c2 = (lane & 3) * 2;
    #pragma unroll
    for (int i = 0; i < 4; i++) {
        #pragma unroll
        for (int jn = 0; jn < 4; jn++) {
            int s = s0 + wm * 64 + i * 16 + g;
            int t = t0 + wn * 32 + jn * 8 + c2;
            #pragma unroll
            for (int e = 0; e < 4; e++) {
                int ss = s + (e >> 1) * 8;
                int tt = t + (e & 1);
                stb[(size_t)ss * TT + tt] =
                    (tt >= ss) ? acc[i][jn][e] * SCALE : -INFINITY;
            }
        }
    }
}

// ---------------------------------------------------------------------------
// K3: single-pass online softmax stats per (b,s) over t in [s, T).
// m init -1e30 (finite sentinel) avoids inf-inf NaN on empty partials.
// ---------------------------------------------------------------------------
__global__ __launch_bounds__(256) void stats_kernel()
{
    const int s = blockIdx.x;
    const int b = blockIdx.y;
    const float* row = g_st + (size_t)b * TT * TT + (size_t)s * TT;
    const int tid = threadIdx.x;

    __shared__ float rm[256], rdn[256];

    float m = -1e30f, d = 0.0f;
    for (int t = s + tid; t < TT; t += 256) {
        float v = row[t];
        float mn = fmaxf(m, v);
        d = d * __expf(m - mn) + __expf(v - mn);
        m = mn;
    }
    rm[tid] = m; rdn[tid] = d;
    __syncthreads();
    for (int off = 128; off > 0; off >>= 1) {
        if (tid < off) {
            float m2 = rm[tid + off], d2 = rdn[tid + off];
            float mn = fmaxf(rm[tid], m2);
            rdn[tid] = rdn[tid] * __expf(rm[tid] - mn) + d2 * __expf(m2 - mn);
            rm[tid] = mn;
        }
        __syncthreads();
    }
    if (tid == 0) {
        g_m[b * TT + s]  = rm[0];
        g_rd[b * TT + s] = 1.0f / rdn[0];
    }
}

// ---------------------------------------------------------------------------
// K4: split-K out partials via mma.sync + ldmatrix.trans. grid = (T/128, NS, B).
// ---------------------------------------------------------------------------
__global__ __launch_bounds__(256) void out_mma_kernel()
{
    const int b  = blockIdx.z;
    const int t0 = blockIdx.x * 128;
    const int js = blockIdx.y;

    const int s_begin = js * SLEN;
    const int s_end_v = (js + 1) * SLEN;
    const int s_end   = (s_end_v < t0 + 128) ? s_end_v : (t0 + 128);
    if (s_begin >= s_end) return;

    __shared__ __align__(16) __nv_bfloat16 smem[4 * 32 * PADT];  // Phi|Plo|Vhi|Vlo

    const float* stb = g_st + (size_t)b * TT * TT;
    const __nv_bfloat16* vhi = g_vhi + (size_t)b * TT * HH;
    const __nv_bfloat16* vlo = g_vlo + (size_t)b * TT * HH;
    const float* mp  = g_m + b * TT;
    const float* rdp = g_rd + b * TT;
    float* part = g_part + ((size_t)js * BB + b) * TT * HH;

    const int tid  = threadIdx.x;
    const int wid  = tid >> 5;
    const int lane = tid & 31;
    const int wm   = wid & 1;    // t-half
    const int wn   = wid >> 1;   // h-quarter
    const uint32_t sbase = smem_u32(smem);
    const uint32_t OPHI = 0u, OPLO = 32u * PADT * 2u,
                   OVHI = 64u * PADT * 2u, OVLO = 96u * PADT * 2u;

    float acc[4][4][4] = {};

    for (int sc = s_begin; sc < s_end; sc += 32) {
        #pragma unroll
        for (int i = 0; i < 16; i++) {
            int idx = tid + i * 256;
            int ss = idx >> 7, ttl = idx & 127;
            int s = sc + ss;
            float val = stb[(size_t)s * TT + t0 + ttl];
            float p = __expf(val - mp[s]) * rdp[s];    // exp(-inf)=0 masks
            __nv_bfloat16 hi = __float2bfloat16(p);
            __nv_bfloat16 lo = __float2bfloat16(p - __bfloat162float(hi));
            smem[ss * PADT + ttl] = hi;
            smem[32 * PADT + ss * PADT + ttl] = lo;
        }
        #pragma unroll
        for (int i = 0; i < 2; i++) {
            int v = tid + i * 256;
            int r = v >> 4, c = v & 15;
            *reinterpret_cast<uint4*>(smem + 64 * PADT + r * PADT + c * 8) =
                *reinterpret_cast<const uint4*>(vhi + (size_t)(sc + r) * HH + c * 8);
            *reinterpret_cast<uint4*>(smem + 96 * PADT + r * PADT + c * 8) =
                *reinterpret_cast<const uint4*>(vlo + (size_t)(sc + r) * HH + c * 8);
        }
        __syncthreads();

        #pragma unroll
        for (int ks = 0; ks < 2; ks++) {
            const int k0 = ks * 16;
            uint32_t a_hi[4][4], a_lo[4][4], b_hi[2][4], b_lo[2][4];

            const int arow = k0 + (lane & 7) + ((lane >> 4) << 3);
            const int acoff = ((lane >> 3) & 1) * 8;
            #pragma unroll
            for (int i = 0; i < 4; i++) {
                uint32_t off = (uint32_t)(arow * PADT + wm * 64 + i * 16 + acoff) * 2;
                ldsm4t(a_hi[i], sbase + OPHI + off);
                ldsm4t(a_lo[i], sbase + OPLO + off);
            }

            const int brow = k0 + (lane & 7) + (((lane >> 3) & 1) << 3);
            const int bcoff = ((lane >> 4) << 3);
            #pragma unroll
            for (int j = 0; j < 2; j++) {
                uint32_t off = (uint32_t)(brow * PADT + wn * 32 + j * 16 + bcoff) * 2;
                ldsm4t(b_hi[j], sbase + OVHI + off);
                ldsm4t(b_lo[j], sbase + OVLO + off);
            }

            #pragma unroll
            for (int i = 0; i < 4; i++) {
                #pragma unroll
                for (int jn = 0; jn < 4; jn++) {
                    uint32_t b0h = b_hi[jn >> 1][(jn & 1) * 2];
                    uint32_t b1h = b_hi[jn >> 1][(jn & 1) * 2 + 1];
                    uint32_t b0l = b_lo[jn >> 1][(jn & 1) * 2];
                    uint32_t b1l = b_lo[jn >> 1][(jn & 1) * 2 + 1];
                    mma16816(acc[i][jn], a_hi[i], b0h, b1h);   // hh
                    mma16816(acc[i][jn], a_lo[i], b0h, b1h);   // lh
                    mma16816(acc[i][jn], a_hi[i], b0l, b1l);   // hl
                }
            }
        }
        __syncthreads();
    }

    const int g  = lane >> 2;
    const int c2 = (lane & 3) * 2;
    #pragma unroll
    for (int i = 0; i < 4; i++) {
        #pragma unroll
        for (int jn = 0; jn < 4; jn++) {
            int t = t0 + wm * 64 + i * 16 + g;
            int h = wn * 32 + jn * 8 + c2;
            #pragma unroll
            for (int e = 0; e < 4; e++) {
                int tt = t + (e >> 1) * 8;
                int hh = h + (e & 1);
                part[(size_t)tt * HH + hh] = acc[i][jn][e];
            }
        }
    }
}

// ---------------------------------------------------------------------------
// K5: reduce partials -> out
// ---------------------------------------------------------------------------
__global__ __launch_bounds__(256) void reduce_kernel(float* __restrict__ out)
{
    const int idx = blockIdx.x * 256 + threadIdx.x;
    const int h = idx & (HH - 1);
    const int t = (idx >> 7) & (TT - 1);
    const int b = idx >> 18;

    const int tile_end = ((t >> 7) + 1) << 7;
    const int nact = (tile_end + SLEN - 1) / SLEN;

    float sum = 0.0f;
    const size_t off = (size_t)b * TT * HH + (size_t)t * HH + h;
    #pragma unroll 4
    for (int j = 0; j < nact; j++)
        sum += g_part[(size_t)j * BB * TT * HH + off];
    out[idx] = sum;
}

extern "C" void kernel_launch(void* const* d_in, const int* in_sizes, int n_in,
                              void* d_out, int out_size)
{
    const float* x  = (const float*)d_in[0];
    const float* Wq = (const float*)d_in[1];
    const float* Wk = (const float*)d_in[2];
    const float* Wv = (const float*)d_in[3];
    float* out = (float*)d_out;

    cudaFuncSetAttribute(qkv_mma_kernel,
                         cudaFuncAttributeMaxDynamicSharedMemorySize, SMEM_DYN);
    cudaFuncSetAttribute(st_mma_kernel,
                         cudaFuncAttributeMaxDynamicSharedMemorySize, SMEM_DYN);

    prep_x_kernel<<<(BB * TT * CC) / 256, 256>>>(x);
    prep_w_kernel<<<(3 * HH * CC) / 256, 256>>>(Wq, Wk, Wv);
    qkv_mma_kernel<<<dim3((BB * TT) / 128, 3), 256, SMEM_DYN>>>();
    st_mma_kernel<<<dim3(TT / 128, TT / 128, BB), 256, SMEM_DYN>>>();
    stats_kernel<<<dim3(TT, BB), 256>>>();
    out_mma_kernel<<<dim3(TT / 128, NS, BB), 256>>>();
    reduce_kernel<<<(BB * TT * HH) / 256, 256>>>(out);
}

// round 8
// speedup vs baseline: 3.6404x; 1.1417x over previous
#include <cuda_runtime.h>
#include <cuda_bf16.h>
#include <math.h>
#include <stdint.h>

#define BB 4
#define TT 2048
#define CC 1024
#define HH 128
#define SCALE 0.08838834764831845f  // 1/sqrt(128)

#define NS   8     // split-K segments for out_kernel
#define SLEN 256   // keys per segment

#define PAD  40    // smem row stride (bf16), conflict-free for ldmatrix
#define PADT 136   // smem row stride (bf16) for 128-wide transposed tiles

#define TILE_B   10240u                 // one padded 128x32 bf16 tile
#define STAGE_B  (4u * TILE_B)          // A_hi|A_lo|B_hi|B_lo
#define SMEM_DYN (2u * STAGE_B)         // 2 pipeline stages = 81920 B

// ---------------------------------------------------------------------------
// Device-global scratch
// ---------------------------------------------------------------------------
__device__ __nv_bfloat16 g_vhi[BB * TT * HH];
__device__ __nv_bfloat16 g_vlo[BB * TT * HH];
__device__ __nv_bfloat16 g_qhi[BB * TT * HH];
__device__ __nv_bfloat16 g_qlo[BB * TT * HH];
__device__ __nv_bfloat16 g_khi[BB * TT * HH];
__device__ __nv_bfloat16 g_klo[BB * TT * HH];
__device__ __nv_bfloat16 g_xhi[(size_t)BB * TT * CC];
__device__ __nv_bfloat16 g_xlo[(size_t)BB * TT * CC];
__device__ __nv_bfloat16 g_wthi[3 * HH * CC];   // [y][n][k] = W[k][n]
__device__ __nv_bfloat16 g_wtlo[3 * HH * CC];
__device__ float g_st[(size_t)BB * TT * TT];
__device__ float g_pm[BB * 16 * TT];            // per-(b, t-tile, s) partial max
__device__ float g_pd[BB * 16 * TT];            // per-(b, t-tile, s) partial sumexp
__device__ float g_m[BB * TT];
__device__ float g_rd[BB * TT];
__device__ float g_part[(size_t)NS * BB * TT * HH];

// ---------------------------------------------------------------------------
// PTX helpers (baseline sm_80-level PTX, compiles under compute_103)
// ---------------------------------------------------------------------------
__device__ __forceinline__ uint32_t smem_u32(const void* p) {
    uint32_t a;
    asm("{ .reg .u64 t; cvta.to.shared.u64 t, %1; cvt.u32.u64 %0, t; }"
        : "=r"(a) : "l"(p));
    return a;
}

__device__ __forceinline__ void ldsm4(uint32_t r[4], uint32_t addr) {
    asm volatile("ldmatrix.sync.aligned.m8n8.x4.shared.b16 {%0,%1,%2,%3}, [%4];"
                 : "=r"(r[0]), "=r"(r[1]), "=r"(r[2]), "=r"(r[3]) : "r"(addr));
}

__device__ __forceinline__ void ldsm4t(uint32_t r[4], uint32_t addr) {
    asm volatile("ldmatrix.sync.aligned.m8n8.x4.trans.shared.b16 {%0,%1,%2,%3}, [%4];"
                 : "=r"(r[0]), "=r"(r[1]), "=r"(r[2]), "=r"(r[3]) : "r"(addr));
}

__device__ __forceinline__ void mma16816(float d[4], const uint32_t a[4],
                                         uint32_t b0, uint32_t b1) {
    asm volatile(
        "mma.sync.aligned.m16n8k16.row.col.f32.bf16.bf16.f32 "
        "{%0,%1,%2,%3}, {%4,%5,%6,%7}, {%8,%9}, {%0,%1,%2,%3};"
        : "+f"(d[0]), "+f"(d[1]), "+f"(d[2]), "+f"(d[3])
        : "r"(a[0]), "r"(a[1]), "r"(a[2]), "r"(a[3]), "r"(b0), "r"(b1));
}

__device__ __forceinline__ void cp16(uint32_t saddr, const void* gptr) {
    asm volatile("cp.async.cg.shared.global [%0], [%1], 16;"
                 :: "r"(saddr), "l"(gptr));
}
#define CP_COMMIT() asm volatile("cp.async.commit_group;" ::: "memory")
#define CP_WAIT1()  asm volatile("cp.async.wait_group 1;" ::: "memory")
#define CP_WAIT0()  asm volatile("cp.async.wait_group 0;" ::: "memory")

// online-softmax merge with finite sentinel (m init -1e30; never -inf - -inf)
__device__ __forceinline__ void sm_merge(float& m, float& d, float m2, float d2) {
    float mn = fmaxf(m, m2);
    d = d * __expf(m - mn) + d2 * __expf(m2 - mn);
    m = mn;
}

// Async-load 4 tiles (A_hi|A_lo|B_hi|B_lo, 128x32 each, leading dim ld).
__device__ __forceinline__ void load4_async(
    const __nv_bfloat16* __restrict__ Ahi, const __nv_bfloat16* __restrict__ Alo,
    const __nv_bfloat16* __restrict__ Bhi, const __nv_bfloat16* __restrict__ Blo,
    int ld, uint32_t sb, int tid)
{
    #pragma unroll
    for (int i = 0; i < 2; i++) {
        int v = tid + i * 256;        // 0..511
        int r = v >> 2, c = v & 3;    // row, 16B chunk
        uint32_t so = (uint32_t)(r * PAD + c * 8) * 2;
        size_t   go = (size_t)r * ld + c * 8;
        cp16(sb + so,              Ahi + go);
        cp16(sb + TILE_B + so,     Alo + go);
        cp16(sb + 2 * TILE_B + so, Bhi + go);
        cp16(sb + 3 * TILE_B + so, Blo + go);
    }
}

// One K=32 chunk (A [m][k], B [n][k], padded PAD) at stage sbase.
__device__ __forceinline__ void gemm_chunk(uint32_t sbase, int lane, int wm, int wn,
                                           float acc[4][4][4]) {
    #pragma unroll
    for (int ks = 0; ks < 2; ks++) {
        const int k0 = ks * 16;
        uint32_t a_hi[4][4], a_lo[4][4], b_hi[2][4], b_lo[2][4];

        const int arow = lane & 15;
        const int acol = k0 + ((lane >> 4) << 3);
        #pragma unroll
        for (int i = 0; i < 4; i++) {
            uint32_t off = (uint32_t)((wm * 64 + i * 16 + arow) * PAD + acol) * 2;
            ldsm4(a_hi[i], sbase + off);
            ldsm4(a_lo[i], sbase + TILE_B + off);
        }

        const int brow = (lane & 7) + ((lane >> 4) << 3);
        const int bcol = k0 + ((lane >> 3) & 1) * 8;
        #pragma unroll
        for (int j = 0; j < 2; j++) {
            uint32_t off = (uint32_t)((wn * 32 + j * 16 + brow) * PAD + bcol) * 2;
            ldsm4(b_hi[j], sbase + 2 * TILE_B + off);
            ldsm4(b_lo[j], sbase + 3 * TILE_B + off);
        }

        #pragma unroll
        for (int i = 0; i < 4; i++) {
            #pragma unroll
            for (int jn = 0; jn < 4; jn++) {
                uint32_t b0h = b_hi[jn >> 1][(jn & 1) * 2];
                uint32_t b1h = b_hi[jn >> 1][(jn & 1) * 2 + 1];
                uint32_t b0l = b_lo[jn >> 1][(jn & 1) * 2];
                uint32_t b1l = b_lo[jn >> 1][(jn & 1) * 2 + 1];
                mma16816(acc[i][jn], a_hi[i], b0h, b1h);   // hh
                mma16816(acc[i][jn], a_lo[i], b0h, b1h);   // lh
                mma16816(acc[i][jn], a_hi[i], b0l, b1l);   // hl
            }
        }
    }
}

// ---------------------------------------------------------------------------
// P0a/P0b: input splits
// ---------------------------------------------------------------------------
__global__ __launch_bounds__(256) void prep_x_kernel(const float* __restrict__ x)
{
    size_t i = (size_t)blockIdx.x * 256 + threadIdx.x;
    float f = x[i];
    __nv_bfloat16 hi = __float2bfloat16(f);
    g_xhi[i] = hi;
    g_xlo[i] = __float2bfloat16(f - __bfloat162float(hi));
}

__global__ __launch_bounds__(256) void prep_w_kernel(
    const float* __restrict__ Wq, const float* __restrict__ Wk, const float* __restrict__ Wv)
{
    int i = blockIdx.x * 256 + threadIdx.x;      // 3*128*1024
    int k = i & (CC - 1);
    int n = (i >> 10) & (HH - 1);
    int y = i >> 17;
    const float* W = (y == 0) ? Wq : (y == 1) ? Wk : Wv;
    float f = W[(size_t)k * HH + n];
    __nv_bfloat16 hi = __float2bfloat16(f);
    g_wthi[i] = hi;
    g_wtlo[i] = __float2bfloat16(f - __bfloat162float(hi));
}

// ---------------------------------------------------------------------------
// K1: QKV projection, cp.async pipelined; epilogue staged via smem for
// coalesced uint4 stores. grid = (B*T/128, 3), 256 threads, dyn smem 80KB.
// ---------------------------------------------------------------------------
__global__ __launch_bounds__(256) void qkv_mma_kernel()
{
    extern __shared__ __align__(16) uint8_t dynsmem[];

    const int tid  = threadIdx.x;
    const int wid  = tid >> 5;
    const int lane = tid & 31;
    const int wm   = wid & 1;
    const int wn   = wid >> 1;
    const int y    = blockIdx.y;
    const int row0 = blockIdx.x * 128;
    const uint32_t sb0 = smem_u32(dynsmem);

    const __nv_bfloat16* Ahi = g_xhi + (size_t)row0 * CC;
    const __nv_bfloat16* Alo = g_xlo + (size_t)row0 * CC;
    const __nv_bfloat16* Bhi = g_wthi + (size_t)y * HH * CC;
    const __nv_bfloat16* Blo = g_wtlo + (size_t)y * HH * CC;

    float acc[4][4][4] = {};
    const int NC = CC / 32;

    load4_async(Ahi, Alo, Bhi, Blo, CC, sb0, tid);
    CP_COMMIT();

    for (int kc = 0; kc < NC; kc++) {
        if (kc + 1 < NC) {
            const int k1 = (kc + 1) * 32;
            load4_async(Ahi + k1, Alo + k1, Bhi + k1, Blo + k1, CC,
                        sb0 + ((kc + 1) & 1) * STAGE_B, tid);
            CP_COMMIT();
            CP_WAIT1();
        } else {
            CP_WAIT0();
        }
        __syncthreads();
        gemm_chunk(sb0 + (kc & 1) * STAGE_B, lane, wm, wn, acc);
        __syncthreads();
    }

    // Epilogue: split to bf16 hi/lo, repack through smem, coalesced stores.
    // smem planes: u32[128][68] hi, then lo. bank = (4*g + col) % 32: conflict-free.
    uint32_t* smu = reinterpret_cast<uint32_t*>(dynsmem);
    const int g = lane >> 2;
    const int q = lane & 3;
    #pragma unroll
    for (int i = 0; i < 4; i++) {
        #pragma unroll
        for (int jn = 0; jn < 4; jn++) {
            #pragma unroll
            for (int erow = 0; erow < 2; erow++) {
                int row  = wm * 64 + i * 16 + g + erow * 8;
                int colu = wn * 16 + jn * 4 + q;
                float v0 = acc[i][jn][erow * 2];
                float v1 = acc[i][jn][erow * 2 + 1];
                __nv_bfloat16 h0 = __float2bfloat16(v0);
                __nv_bfloat16 h1 = __float2bfloat16(v1);
                __nv_bfloat16 l0 = __float2bfloat16(v0 - __bfloat162float(h0));
                __nv_bfloat16 l1 = __float2bfloat16(v1 - __bfloat162float(h1));
                uint32_t hp = (uint32_t)__bfloat16_as_ushort(h0)
                            | ((uint32_t)__bfloat16_as_ushort(h1) << 16);
                uint32_t lp = (uint32_t)__bfloat16_as_ushort(l0)
                            | ((uint32_t)__bfloat16_as_ushort(l1) << 16);
                smu[row * 68 + colu] = hp;
                smu[128 * 68 + row * 68 + colu] = lp;
            }
        }
    }
    __syncthreads();

    __nv_bfloat16* dhi = (y == 0) ? g_qhi : (y == 1) ? g_khi : g_vhi;
    __nv_bfloat16* dlo = (y == 0) ? g_qlo : (y == 1) ? g_klo : g_vlo;
    const uint4* s4 = reinterpret_cast<const uint4*>(dynsmem);
    #pragma unroll
    for (int it = 0; it < 8; it++) {
        int v = tid + it * 256;         // 0..2047
        int row = v >> 4, c4 = v & 15;
        *reinterpret_cast<uint4*>(dhi + (size_t)(row0 + row) * HH + c4 * 8) =
            s4[row * 17 + c4];
        *reinterpret_cast<uint4*>(dlo + (size_t)(row0 + row) * HH + c4 * 8) =
            s4[128 * 17 + row * 17 + c4];
    }
}

// ---------------------------------------------------------------------------
// K2: ST tile + fused per-tile softmax partial stats.
// Writes ST (float2), and per-(b, t-tile, s) partial (max, sumexp) to g_pm/g_pd.
// grid = (T/128 t-tiles, T/128 s-tiles, B), dyn smem 80KB.
// ---------------------------------------------------------------------------
__global__ __launch_bounds__(256) void st_mma_kernel()
{
    const int b  = blockIdx.z;
    const int t0 = blockIdx.x * 128;
    const int s0 = blockIdx.y * 128;
    if (t0 + 127 < s0) return;

    extern __shared__ __align__(16) uint8_t dynsmem[];

    const int tid  = threadIdx.x;
    const int wid  = tid >> 5;
    const int lane = tid & 31;
    const int wm   = wid & 1;
    const int wn   = wid >> 1;
    const uint32_t sb0 = smem_u32(dynsmem);

    const __nv_bfloat16* Ahi = g_khi + ((size_t)b * TT + s0) * HH;
    const __nv_bfloat16* Alo = g_klo + ((size_t)b * TT + s0) * HH;
    const __nv_bfloat16* Bhi = g_qhi + ((size_t)b * TT + t0) * HH;
    const __nv_bfloat16* Blo = g_qlo + ((size_t)b * TT + t0) * HH;

    float acc[4][4][4] = {};
    const int NC = HH / 32;

    load4_async(Ahi, Alo, Bhi, Blo, HH, sb0, tid);
    CP_COMMIT();

    for (int kc = 0; kc < NC; kc++) {
        if (kc + 1 < NC) {
            const int k1 = (kc + 1) * 32;
            load4_async(Ahi + k1, Alo + k1, Bhi + k1, Blo + k1, HH,
                        sb0 + ((kc + 1) & 1) * STAGE_B, tid);
            CP_COMMIT();
            CP_WAIT1();
        } else {
            CP_WAIT0();
        }
        __syncthreads();
        gemm_chunk(sb0 + (kc & 1) * STAGE_B, lane, wm, wn, acc);
        __syncthreads();
    }

    float* stb = g_st + (size_t)b * TT * TT;
    const int g  = lane >> 2;
    const int c2 = (lane & 3) * 2;

    float pm[8], pd[8];   // per (i, erow) = per local s-row
    #pragma unroll
    for (int k8 = 0; k8 < 8; k8++) { pm[k8] = -1e30f; pd[k8] = 0.0f; }

    #pragma unroll
    for (int i = 0; i < 4; i++) {
        #pragma unroll
        for (int jn = 0; jn < 4; jn++) {
            int ssb = s0 + wm * 64 + i * 16 + g;
            int tt0 = t0 + wn * 32 + jn * 8 + c2;
            #pragma unroll
            for (int erow = 0; erow < 2; erow++) {
                int ss = ssb + erow * 8;
                float v0 = acc[i][jn][erow * 2]     * SCALE;
                float v1 = acc[i][jn][erow * 2 + 1] * SCALE;
                float2 w;
                w.x = (tt0     >= ss) ? v0 : -INFINITY;
                w.y = (tt0 + 1 >= ss) ? v1 : -INFINITY;
                *reinterpret_cast<float2*>(&stb[(size_t)ss * TT + tt0]) = w;
                int k8 = i * 2 + erow;
                if (tt0 >= ss) {
                    float mn = fmaxf(pm[k8], v0);
                    pd[k8] = pd[k8] * __expf(pm[k8] - mn) + __expf(v0 - mn);
                    pm[k8] = mn;
                }
                if (tt0 + 1 >= ss) {
                    float mn = fmaxf(pm[k8], v1);
                    pd[k8] = pd[k8] * __expf(pm[k8] - mn) + __expf(v1 - mn);
                    pm[k8] = mn;
                }
            }
        }
    }

    // quad reduce (lanes sharing g hold same s-row, different t)
    #pragma unroll
    for (int k8 = 0; k8 < 8; k8++) {
        #pragma unroll
        for (int off = 1; off <= 2; off <<= 1) {
            float m2 = __shfl_xor_sync(0xffffffffu, pm[k8], off);
            float d2 = __shfl_xor_sync(0xffffffffu, pd[k8], off);
            sm_merge(pm[k8], pd[k8], m2, d2);
        }
    }

    // cross-warp (wn) merge via smem: [128 s-rows][4 wn] m then d
    float* smf = reinterpret_cast<float*>(dynsmem);
    if ((lane & 3) == 0) {
        #pragma unroll
        for (int k8 = 0; k8 < 8; k8++) {
            int r = wm * 64 + (k8 >> 1) * 16 + g + (k8 & 1) * 8;
            smf[r * 4 + wn]       = pm[k8];
            smf[512 + r * 4 + wn] = pd[k8];
        }
    }
    __syncthreads();
    if (tid < 128) {
        float m = -1e30f, d = 0.0f;
        #pragma unroll
        for (int w = 0; w < 4; w++)
            sm_merge(m, d, smf[tid * 4 + w], smf[512 + tid * 4 + w]);
        size_t o = (((size_t)b * 16 + blockIdx.x) << 11) + s0 + tid;
        g_pm[o] = m;
        g_pd[o] = d;
    }
}

// ---------------------------------------------------------------------------
// K3: merge per-t-tile partials -> g_m, g_rd. t-tile jt active iff jt >= s>>7.
// grid = B*T/256.
// ---------------------------------------------------------------------------
__global__ __launch_bounds__(256) void merge_stats_kernel()
{
    int idx = blockIdx.x * 256 + threadIdx.x;   // over B*T
    int b = idx >> 11;
    int s = idx & (TT - 1);

    float m = -1e30f, d = 0.0f;
    for (int jt = s >> 7; jt < 16; jt++) {
        size_t o = (((size_t)b * 16 + jt) << 11) + s;
        sm_merge(m, d, g_pm[o], g_pd[o]);
    }
    g_m[idx]  = m;
    g_rd[idx] = 1.0f / d;
}

// ---------------------------------------------------------------------------
// K4: split-K out partials via mma.sync + ldmatrix.trans. grid = (T/128, NS, B).
// ---------------------------------------------------------------------------
__global__ __launch_bounds__(256) void out_mma_kernel()
{
    const int b  = blockIdx.z;
    const int t0 = blockIdx.x * 128;
    const int js = blockIdx.y;

    const int s_begin = js * SLEN;
    const int s_end_v = (js + 1) * SLEN;
    const int s_end   = (s_end_v < t0 + 128) ? s_end_v : (t0 + 128);
    if (s_begin >= s_end) return;

    __shared__ __align__(16) __nv_bfloat16 smem[4 * 32 * PADT];  // Phi|Plo|Vhi|Vlo

    const float* stb = g_st + (size_t)b * TT * TT;
    const __nv_bfloat16* vhi = g_vhi + (size_t)b * TT * HH;
    const __nv_bfloat16* vlo = g_vlo + (size_t)b * TT * HH;
    const float* mp  = g_m + b * TT;
    const float* rdp = g_rd + b * TT;
    float* part = g_part + ((size_t)js * BB + b) * TT * HH;

    const int tid  = threadIdx.x;
    const int wid  = tid >> 5;
    const int lane = tid & 31;
    const int wm   = wid & 1;    // t-half
    const int wn   = wid >> 1;   // h-quarter
    const uint32_t sbase = smem_u32(smem);
    const uint32_t OPHI = 0u, OPLO = 32u * PADT * 2u,
                   OVHI = 64u * PADT * 2u, OVLO = 96u * PADT * 2u;

    float acc[4][4][4] = {};

    for (int sc = s_begin; sc < s_end; sc += 32) {
        #pragma unroll
        for (int i = 0; i < 16; i++) {
            int idx = tid + i * 256;
            int ss = idx >> 7, ttl = idx & 127;
            int s = sc + ss;
            float val = stb[(size_t)s * TT + t0 + ttl];
            float p = __expf(val - mp[s]) * rdp[s];    // exp(-inf)=0 masks
            __nv_bfloat16 hi = __float2bfloat16(p);
            __nv_bfloat16 lo = __float2bfloat16(p - __bfloat162float(hi));
            smem[ss * PADT + ttl] = hi;
            smem[32 * PADT + ss * PADT + ttl] = lo;
        }
        #pragma unroll
        for (int i = 0; i < 2; i++) {
            int v = tid + i * 256;
            int r = v >> 4, c = v & 15;
            *reinterpret_cast<uint4*>(smem + 64 * PADT + r * PADT + c * 8) =
                *reinterpret_cast<const uint4*>(vhi + (size_t)(sc + r) * HH + c * 8);
            *reinterpret_cast<uint4*>(smem + 96 * PADT + r * PADT + c * 8) =
                *reinterpret_cast<const uint4*>(vlo + (size_t)(sc + r) * HH + c * 8);
        }
        __syncthreads();

        #pragma unroll
        for (int ks = 0; ks < 2; ks++) {
            const int k0 = ks * 16;
            uint32_t a_hi[4][4], a_lo[4][4], b_hi[2][4], b_lo[2][4];

            const int arow = k0 + (lane & 7) + ((lane >> 4) << 3);
            const int acoff = ((lane >> 3) & 1) * 8;
            #pragma unroll
            for (int i = 0; i < 4; i++) {
                uint32_t off = (uint32_t)(arow * PADT + wm * 64 + i * 16 + acoff) * 2;
                ldsm4t(a_hi[i], sbase + OPHI + off);
                ldsm4t(a_lo[i], sbase + OPLO + off);
            }

            const int brow = k0 + (lane & 7) + (((lane >> 3) & 1) << 3);
            const int bcoff = ((lane >> 4) << 3);
            #pragma unroll
            for (int j = 0; j < 2; j++) {
                uint32_t off = (uint32_t)(brow * PADT + wn * 32 + j * 16 + bcoff) * 2;
                ldsm4t(b_hi[j], sbase + OVHI + off);
                ldsm4t(b_lo[j], sbase + OVLO + off);
            }

            #pragma unroll
            for (int i = 0; i < 4; i++) {
                #pragma unroll
                for (int jn = 0; jn < 4; jn++) {
                    uint32_t b0h = b_hi[jn >> 1][(jn & 1) * 2];
                    uint32_t b1h = b_hi[jn >> 1][(jn & 1) * 2 + 1];
                    uint32_t b0l = b_lo[jn >> 1][(jn & 1) * 2];
                    uint32_t b1l = b_lo[jn >> 1][(jn & 1) * 2 + 1];
                    mma16816(acc[i][jn], a_hi[i], b0h, b1h);   // hh
                    mma16816(acc[i][jn], a_lo[i], b0h, b1h);   // lh
                    mma16816(acc[i][jn], a_hi[i], b0l, b1l);   // hl
                }
            }
        }
        __syncthreads();
    }

    const int g  = lane >> 2;
    const int c2 = (lane & 3) * 2;
    #pragma unroll
    for (int i = 0; i < 4; i++) {
        #pragma unroll
        for (int jn = 0; jn < 4; jn++) {
            int t = t0 + wm * 64 + i * 16 + g;
            int h = wn * 32 + jn * 8 + c2;
            #pragma unroll
            for (int erow = 0; erow < 2; erow++) {
                float2 w;
                w.x = acc[i][jn][erow * 2];
                w.y = acc[i][jn][erow * 2 + 1];
                *reinterpret_cast<float2*>(
                    &part[(size_t)(t + erow * 8) * HH + h]) = w;
            }
        }
    }
}

// ---------------------------------------------------------------------------
// K5: reduce partials -> out
// ---------------------------------------------------------------------------
__global__ __launch_bounds__(256) void reduce_kernel(float* __restrict__ out)
{
    const int idx = blockIdx.x * 256 + threadIdx.x;
    const int h = idx & (HH - 1);
    const int t = (idx >> 7) & (TT - 1);
    const int b = idx >> 18;

    const int tile_end = ((t >> 7) + 1) << 7;
    const int nact = (tile_end + SLEN - 1) / SLEN;

    float sum = 0.0f;
    const size_t off = (size_t)b * TT * HH + (size_t)t * HH + h;
    #pragma unroll 4
    for (int j = 0; j < nact; j++)
        sum += g_part[(size_t)j * BB * TT * HH + off];
    out[idx] = sum;
}

extern "C" void kernel_launch(void* const* d_in, const int* in_sizes, int n_in,
                              void* d_out, int out_size)
{
    const float* x  = (const float*)d_in[0];
    const float* Wq = (const float*)d_in[1];
    const float* Wk = (const float*)d_in[2];
    const float* Wv = (const float*)d_in[3];
    float* out = (float*)d_out;

    cudaFuncSetAttribute(qkv_mma_kernel,
                         cudaFuncAttributeMaxDynamicSharedMemorySize, SMEM_DYN);
    cudaFuncSetAttribute(st_mma_kernel,
                         cudaFuncAttributeMaxDynamicSharedMemorySize, SMEM_DYN);

    prep_x_kernel<<<(BB * TT * CC) / 256, 256>>>(x);
    prep_w_kernel<<<(3 * HH * CC) / 256, 256>>>(Wq, Wk, Wv);
    qkv_mma_kernel<<<dim3((BB * TT) / 128, 3), 256, SMEM_DYN>>>();
    st_mma_kernel<<<dim3(TT / 128, TT / 128, BB), 256, SMEM_DYN>>>();
    merge_stats_kernel<<<(BB * TT) / 256, 256>>>();
    out_mma_kernel<<<dim3(TT / 128, NS, BB), 256>>>();
    reduce_kernel<<<(BB * TT * HH) / 256, 256>>>(out);
}